// round 3
// baseline (speedup 1.0000x reference)
#include <cuda_runtime.h>

#define NNODES 100000
#define NEDGES 500000
#define DIM 128
#define NHEADS 4

// ---------------- scratch (no allocations allowed) ----------------
__device__ float g_h[NNODES * DIM];          // 51.2 MB
__device__ float g_asrc[NNODES * NHEADS];    // 1.6 MB
__device__ float g_adst[NNODES * NHEADS];    // 1.6 MB (b_att folded in)
__device__ float g_logits[NEDGES * NHEADS];  // 8 MB
__device__ unsigned g_max_u[NHEADS];
__device__ float g_maxf[NHEADS];
__device__ float g_sum[NHEADS];
__device__ float g_inv[NHEADS];

// order-preserving float<->uint encoding for atomicMax
__device__ __forceinline__ unsigned encf(float f) {
    unsigned u = __float_as_uint(f);
    return (u & 0x80000000u) ? ~u : (u | 0x80000000u);
}
__device__ __forceinline__ float decf(unsigned u) {
    u = (u & 0x80000000u) ? (u & 0x7FFFFFFFu) : ~u;
    return __uint_as_float(u);
}

// ---------------- K0: init accumulators ----------------
__global__ void init_kernel() {
    int t = threadIdx.x;
    if (t < NHEADS) { g_max_u[t] = 0u; g_sum[t] = 0.0f; }
}

// ---------------- K1: h = feat @ W^T + b, out = h, alphas ----------------
// 256 threads = 8 warps; each warp computes one full 128-dim node row,
// lane covers 4 consecutive output cols via float4. W transposed in smem.
__global__ void gemm_kernel(const float* __restrict__ feat,
                            const float* __restrict__ W,
                            const float* __restrict__ b,
                            const float* __restrict__ Wa_g,
                            const float* __restrict__ ba,
                            float* __restrict__ out) {
    extern __shared__ float sm[];
    float* Wt   = sm;                       // [128][128] transposed: Wt[k*128+j] = W[j*128+k]
    float* bias = Wt + DIM * DIM;           // [128]
    float* Wa   = bias + DIM;               // [4][256]
    float* fbuf = Wa + NHEADS * 2 * DIM;    // [8][128] per-warp feature row

    for (int i = threadIdx.x; i < DIM * DIM; i += blockDim.x) {
        int j = i >> 7, k = i & 127;
        Wt[k * DIM + j] = W[i];
    }
    for (int i = threadIdx.x; i < DIM; i += blockDim.x) bias[i] = b[i];
    for (int i = threadIdx.x; i < NHEADS * 2 * DIM; i += blockDim.x) Wa[i] = Wa_g[i];
    __syncthreads();

    int warp = threadIdx.x >> 5, lane = threadIdx.x & 31;
    float* fw = fbuf + warp * DIM;

    for (int n = blockIdx.x * 8 + warp; n < NNODES; n += gridDim.x * 8) {
        ((float4*)fw)[lane] = ((const float4*)(feat + (size_t)n * DIM))[lane];
        __syncwarp();

        float4 acc = ((const float4*)bias)[lane];
#pragma unroll 16
        for (int k = 0; k < DIM; k++) {
            float fk = fw[k];                                   // smem broadcast
            float4 w = ((const float4*)(Wt + k * DIM))[lane];   // conflict-free float4
            acc.x = fmaf(fk, w.x, acc.x);
            acc.y = fmaf(fk, w.y, acc.y);
            acc.z = fmaf(fk, w.z, acc.z);
            acc.w = fmaf(fk, w.w, acc.w);
        }

        ((float4*)(out + (size_t)n * DIM))[lane] = acc;   // out starts as h
        ((float4*)(g_h + (size_t)n * DIM))[lane] = acc;   // stable copy for scatter reads

        // alphas: per-head dot(h, Wa1) and dot(h, Wa2)+b_att
#pragma unroll
        for (int h = 0; h < NHEADS; h++) {
            float4 ws = ((const float4*)(Wa + h * 2 * DIM))[lane];
            float4 wd = ((const float4*)(Wa + h * 2 * DIM + DIM))[lane];
            float ps = acc.x * ws.x + acc.y * ws.y + acc.z * ws.z + acc.w * ws.w;
            float pd = acc.x * wd.x + acc.y * wd.y + acc.z * wd.z + acc.w * wd.w;
#pragma unroll
            for (int o = 16; o; o >>= 1) {
                ps += __shfl_down_sync(0xffffffffu, ps, o);
                pd += __shfl_down_sync(0xffffffffu, pd, o);
            }
            if (lane == 0) {
                g_asrc[n * NHEADS + h] = ps;
                g_adst[n * NHEADS + h] = pd + ba[h];
            }
        }
        __syncwarp();
    }
}

// ---------------- K2: logits + global per-head max ----------------
__global__ void logits_max_kernel(const int* __restrict__ ei) {
    const int* src = ei;
    const int* dst = ei + NEDGES;
    float m0 = -1e30f, m1 = -1e30f, m2 = -1e30f, m3 = -1e30f;
    int stride = gridDim.x * blockDim.x;
    for (int e = blockIdx.x * blockDim.x + threadIdx.x; e < NEDGES; e += stride) {
        int s = src[e], d = dst[e];
        float4 as = *(const float4*)(g_asrc + (size_t)s * 4);
        float4 ad = *(const float4*)(g_adst + (size_t)d * 4);
        float4 l;
        l.x = as.x + ad.x; l.y = as.y + ad.y;
        l.z = as.z + ad.z; l.w = as.w + ad.w;
        *(float4*)(g_logits + (size_t)e * 4) = l;
        m0 = fmaxf(m0, l.x); m1 = fmaxf(m1, l.y);
        m2 = fmaxf(m2, l.z); m3 = fmaxf(m3, l.w);
    }
    __shared__ float red[4][8];
    int lane = threadIdx.x & 31, w = threadIdx.x >> 5;
#pragma unroll
    for (int o = 16; o; o >>= 1) {
        m0 = fmaxf(m0, __shfl_down_sync(0xffffffffu, m0, o));
        m1 = fmaxf(m1, __shfl_down_sync(0xffffffffu, m1, o));
        m2 = fmaxf(m2, __shfl_down_sync(0xffffffffu, m2, o));
        m3 = fmaxf(m3, __shfl_down_sync(0xffffffffu, m3, o));
    }
    if (lane == 0) { red[0][w] = m0; red[1][w] = m1; red[2][w] = m2; red[3][w] = m3; }
    __syncthreads();
    if (threadIdx.x < 4) {
        float mm = red[threadIdx.x][0];
#pragma unroll
        for (int i = 1; i < 8; i++) mm = fmaxf(mm, red[threadIdx.x][i]);
        atomicMax(&g_max_u[threadIdx.x], encf(mm));
    }
}

// ---------------- K3: per-head sum of exp ----------------
__global__ void sum_kernel() {
    float mx0 = decf(g_max_u[0]), mx1 = decf(g_max_u[1]);
    float mx2 = decf(g_max_u[2]), mx3 = decf(g_max_u[3]);
    float s0 = 0.f, s1 = 0.f, s2 = 0.f, s3 = 0.f;
    int stride = gridDim.x * blockDim.x;
    for (int e = blockIdx.x * blockDim.x + threadIdx.x; e < NEDGES; e += stride) {
        float4 l = *(const float4*)(g_logits + (size_t)e * 4);
        s0 += __expf(l.x - mx0); s1 += __expf(l.y - mx1);
        s2 += __expf(l.z - mx2); s3 += __expf(l.w - mx3);
    }
    __shared__ float red[4][8];
    int lane = threadIdx.x & 31, w = threadIdx.x >> 5;
#pragma unroll
    for (int o = 16; o; o >>= 1) {
        s0 += __shfl_down_sync(0xffffffffu, s0, o);
        s1 += __shfl_down_sync(0xffffffffu, s1, o);
        s2 += __shfl_down_sync(0xffffffffu, s2, o);
        s3 += __shfl_down_sync(0xffffffffu, s3, o);
    }
    if (lane == 0) { red[0][w] = s0; red[1][w] = s1; red[2][w] = s2; red[3][w] = s3; }
    __syncthreads();
    if (threadIdx.x < 4) {
        float ss = 0.f;
#pragma unroll
        for (int i = 0; i < 8; i++) ss += red[threadIdx.x][i];
        atomicAdd(&g_sum[threadIdx.x], ss);
    }
}

// ---------------- K3b: finalize softmax denominators ----------------
__global__ void finalize_kernel() {
    int t = threadIdx.x;
    if (t < NHEADS) {
        g_inv[t] = 1.0f / g_sum[t];
        g_maxf[t] = decf(g_max_u[t]);
    }
}

// ---------------- K4: scatter messages ----------------
// warp per edge; lane = feature d in [0,32); 4 heads -> 4 REDs per lane.
__global__ void scatter_kernel(const int* __restrict__ ei,
                               float* __restrict__ out) {
    const int* src = ei;
    const int* dst = ei + NEDGES;
    int lane = threadIdx.x & 31;
    int warpId = (blockIdx.x * blockDim.x + threadIdx.x) >> 5;
    int nw = (gridDim.x * blockDim.x) >> 5;
    float m0 = g_maxf[0], m1 = g_maxf[1], m2 = g_maxf[2], m3 = g_maxf[3];
    float i0 = g_inv[0], i1 = g_inv[1], i2 = g_inv[2], i3 = g_inv[3];

    for (int e = warpId; e < NEDGES; e += nw) {
        int s = src[e], d = dst[e];
        float sv = g_h[(size_t)s * DIM + lane];          // coalesced 128B gather
        float4 l = *(const float4*)(g_logits + (size_t)e * 4);  // broadcast
        float a0 = __expf(l.x - m0) * i0;
        float a1 = __expf(l.y - m1) * i1;
        float a2 = __expf(l.z - m2) * i2;
        float a3 = __expf(l.w - m3) * i3;
        float* o = out + (size_t)d * DIM;
        atomicAdd(o + lane,      a0 * sv);
        atomicAdd(o + 32 + lane, a1 * sv);
        atomicAdd(o + 64 + lane, a2 * sv);
        atomicAdd(o + 96 + lane, a3 * sv);
    }
}

// ---------------- launch ----------------
extern "C" void kernel_launch(void* const* d_in, const int* in_sizes, int n_in,
                              void* d_out, int out_size) {
    const float* feat = (const float*)d_in[0];
    const int*   ei   = (const int*)d_in[1];
    const float* Wlin = (const float*)d_in[2];
    const float* blin = (const float*)d_in[3];
    const float* Watt = (const float*)d_in[4];
    const float* batt = (const float*)d_in[5];
    float* out = (float*)d_out;

    init_kernel<<<1, 32>>>();

    size_t smem = (size_t)(DIM * DIM + DIM + NHEADS * 2 * DIM + 8 * DIM) * sizeof(float);
    cudaFuncSetAttribute(gemm_kernel, cudaFuncAttributeMaxDynamicSharedMemorySize, (int)smem);
    gemm_kernel<<<1480, 256, smem>>>(feat, Wlin, blin, Watt, batt, out);

    logits_max_kernel<<<296, 256>>>(ei);
    sum_kernel<<<296, 256>>>();
    finalize_kernel<<<1, 32>>>();
    scatter_kernel<<<1480, 256>>>(ei, out);
}

// round 5
// speedup vs baseline: 1.6014x; 1.6014x over previous
#include <cuda_runtime.h>

#define NNODES 100000
#define NEDGES 500000
#define DIM 128
#define NHEADS 4
#define NTILES ((NNODES + 63) / 64)
#define SCAN_B ((NNODES + 255) / 256)   // 391

// ---------------- scratch ----------------
__device__ float  g_h[NNODES * DIM];           // 51.2 MB  (h = feat@W^T + b)
__device__ float  g_asrc[NNODES * NHEADS];     // per-node src alphas
__device__ float  g_adst[NNODES * NHEADS];     // per-node dst alphas (+b_att)
__device__ float  g_logits[NEDGES * NHEADS];   // 8 MB
__device__ float  g_va[8 * DIM];               // wa @ W  (4 src rows, 4 dst rows)
__device__ float  g_vc[8];                     // b·wa (+ba for dst part)
__device__ unsigned g_max_u[NHEADS];
__device__ float  g_maxf[NHEADS];
__device__ float  g_sum[NHEADS];
__device__ float  g_inv[NHEADS];
// counting-sort scratch
__device__ int    g_cnt[NNODES];
__device__ int    g_cnt2[NNODES];
__device__ int    g_base[NNODES + 1];
__device__ int    g_part[SCAN_B];
__device__ int    g_poff[SCAN_B];
__device__ int    g_esrc[NEDGES];
__device__ float4 g_ea[NEDGES];                // attn weights per sorted slot

__device__ __forceinline__ unsigned encf(float f) {
    unsigned u = __float_as_uint(f);
    return (u & 0x80000000u) ? ~u : (u | 0x80000000u);
}
__device__ __forceinline__ float decf(unsigned u) {
    u = (u & 0x80000000u) ? (u & 0x7FFFFFFFu) : ~u;
    return __uint_as_float(u);
}

// ---------------- K0: zero counters + init accumulators ----------------
__global__ void zero_kernel() {
    int i = blockIdx.x * blockDim.x + threadIdx.x;
    if (i < NNODES) { g_cnt[i] = 0; g_cnt2[i] = 0; }
    if (i < NHEADS) { g_max_u[i] = 0u; g_sum[i] = 0.0f; }
}

// ---------------- K0b: va = wa @ W, vc = b·wa (+ba) ----------------
// j = part*4 + head ; part 0 = src half of W_att, part 1 = dst half
__global__ void va_kernel(const float* __restrict__ W,
                          const float* __restrict__ b,
                          const float* __restrict__ Wa,
                          const float* __restrict__ ba) {
    int t = threadIdx.x;               // 1024 threads
    int j = t >> 7, i = t & 127;
    int head = j & 3, part = j >> 2;
    const float* war = Wa + head * 2 * DIM + part * DIM;
    float s = 0.f;
    for (int k = 0; k < DIM; k++) s += war[k] * W[k * DIM + i];
    g_va[j * DIM + i] = s;
    if (t < 8) {
        int hh = t & 3, pp = t >> 2;
        const float* wr = Wa + hh * 2 * DIM + pp * DIM;
        float c = 0.f;
        for (int k = 0; k < DIM; k++) c += b[k] * wr[k];
        if (pp) c += ba[hh];
        g_vc[t] = c;
    }
}

// ---------------- K1: register-blocked GEMM  g_h = feat @ W^T + b ----------------
// block = 256 thr; tile = 64 nodes x 128 outs; warp = 8 nodes, lane = 4 outs.
__global__ void gemm_kernel(const float* __restrict__ feat,
                            const float* __restrict__ W,
                            const float* __restrict__ b) {
    extern __shared__ float sm[];
    float* Wt    = sm;                    // [128][128] transposed
    float* bias  = Wt + DIM * DIM;        // [128]
    float* sfeat = bias + DIM;            // [64][132] padded

    for (int i = threadIdx.x; i < DIM * DIM; i += blockDim.x) {
        int j = i >> 7, k = i & 127;
        Wt[k * DIM + j] = W[i];
    }
    for (int i = threadIdx.x; i < DIM; i += blockDim.x) bias[i] = b[i];
    __syncthreads();

    int warp = threadIdx.x >> 5, lane = threadIdx.x & 31;
    const float4* Wt4 = (const float4*)Wt;
    float4 bias4 = ((const float4*)bias)[lane];

    for (int tile = blockIdx.x; tile < NTILES; tile += gridDim.x) {
        int nb = tile * 64;
        __syncthreads();  // protect sfeat from previous iteration
        for (int idx = threadIdx.x; idx < 64 * 32; idx += blockDim.x) {
            int r = idx >> 5, c = idx & 31;
            float4 v = make_float4(0.f, 0.f, 0.f, 0.f);
            if (nb + r < NNODES)
                v = ((const float4*)(feat + (size_t)(nb + r) * DIM))[c];
            *(float4*)(sfeat + r * 132 + c * 4) = v;
        }
        __syncthreads();

        float4 acc[8];
#pragma unroll
        for (int n = 0; n < 8; n++) acc[n] = bias4;

        const float* frow = sfeat + (warp * 8) * 132;
#pragma unroll 4
        for (int k = 0; k < DIM; k++) {
            float4 w = Wt4[k * 32 + lane];
#pragma unroll
            for (int n = 0; n < 8; n++) {
                float f = frow[n * 132 + k];
                acc[n].x = fmaf(f, w.x, acc[n].x);
                acc[n].y = fmaf(f, w.y, acc[n].y);
                acc[n].z = fmaf(f, w.z, acc[n].z);
                acc[n].w = fmaf(f, w.w, acc[n].w);
            }
        }
#pragma unroll
        for (int n = 0; n < 8; n++) {
            int node = nb + warp * 8 + n;
            if (node < NNODES)
                ((float4*)(g_h + (size_t)node * DIM))[lane] = acc[n];
        }
    }
}

// ---------------- K2: alphas = feat · va + vc ----------------
// warp per node; 8 dots of length 128 via shuffle reductions.
__global__ void alpha_kernel(const float* __restrict__ feat) {
    __shared__ float sva[8 * 132];
    __shared__ float svc[8];
    for (int i = threadIdx.x; i < 8 * DIM; i += blockDim.x) {
        int j = i >> 7, k = i & 127;
        sva[j * 132 + k] = g_va[i];
    }
    if (threadIdx.x < 8) svc[threadIdx.x] = g_vc[threadIdx.x];
    __syncthreads();

    int lane = threadIdx.x & 31;
    int w = (blockIdx.x * blockDim.x + threadIdx.x) >> 5;
    int nw = (gridDim.x * blockDim.x) >> 5;
    for (int n = w; n < NNODES; n += nw) {
        float4 f4 = ((const float4*)(feat + (size_t)n * DIM))[lane];
#pragma unroll
        for (int j = 0; j < 8; j++) {
            float4 v = *(const float4*)(sva + j * 132 + lane * 4);
            float p = f4.x * v.x + f4.y * v.y + f4.z * v.z + f4.w * v.w;
#pragma unroll
            for (int o = 16; o; o >>= 1) p += __shfl_down_sync(0xffffffffu, p, o);
            if (lane == 0) {
                if (j < 4) g_asrc[n * NHEADS + j] = p + svc[j];
                else       g_adst[n * NHEADS + (j - 4)] = p + svc[j];
            }
        }
    }
}

// ---------------- K3: logits + per-head max + dst histogram ----------------
__global__ void logits_hist_kernel(const int* __restrict__ ei) {
    const int* src = ei;
    const int* dst = ei + NEDGES;
    float m0 = -1e30f, m1 = -1e30f, m2 = -1e30f, m3 = -1e30f;
    int stride = gridDim.x * blockDim.x;
    for (int e = blockIdx.x * blockDim.x + threadIdx.x; e < NEDGES; e += stride) {
        int s = src[e], d = dst[e];
        atomicAdd(&g_cnt[d], 1);
        float4 as = *(const float4*)(g_asrc + (size_t)s * 4);
        float4 ad = *(const float4*)(g_adst + (size_t)d * 4);
        float4 l;
        l.x = as.x + ad.x; l.y = as.y + ad.y;
        l.z = as.z + ad.z; l.w = as.w + ad.w;
        *(float4*)(g_logits + (size_t)e * 4) = l;
        m0 = fmaxf(m0, l.x); m1 = fmaxf(m1, l.y);
        m2 = fmaxf(m2, l.z); m3 = fmaxf(m3, l.w);
    }
    __shared__ float red[4][8];
    int lane = threadIdx.x & 31, w = threadIdx.x >> 5;
#pragma unroll
    for (int o = 16; o; o >>= 1) {
        m0 = fmaxf(m0, __shfl_down_sync(0xffffffffu, m0, o));
        m1 = fmaxf(m1, __shfl_down_sync(0xffffffffu, m1, o));
        m2 = fmaxf(m2, __shfl_down_sync(0xffffffffu, m2, o));
        m3 = fmaxf(m3, __shfl_down_sync(0xffffffffu, m3, o));
    }
    if (lane == 0) { red[0][w] = m0; red[1][w] = m1; red[2][w] = m2; red[3][w] = m3; }
    __syncthreads();
    if (threadIdx.x < 4) {
        float mm = red[threadIdx.x][0];
#pragma unroll
        for (int i = 1; i < 8; i++) mm = fmaxf(mm, red[threadIdx.x][i]);
        atomicMax(&g_max_u[threadIdx.x], encf(mm));
    }
}

// ---------------- K4: per-head sum of exp ----------------
__global__ void sum_kernel() {
    float mx0 = decf(g_max_u[0]), mx1 = decf(g_max_u[1]);
    float mx2 = decf(g_max_u[2]), mx3 = decf(g_max_u[3]);
    float s0 = 0.f, s1 = 0.f, s2 = 0.f, s3 = 0.f;
    int stride = gridDim.x * blockDim.x;
    for (int e = blockIdx.x * blockDim.x + threadIdx.x; e < NEDGES; e += stride) {
        float4 l = *(const float4*)(g_logits + (size_t)e * 4);
        s0 += __expf(l.x - mx0); s1 += __expf(l.y - mx1);
        s2 += __expf(l.z - mx2); s3 += __expf(l.w - mx3);
    }
    __shared__ float red[4][8];
    int lane = threadIdx.x & 31, w = threadIdx.x >> 5;
#pragma unroll
    for (int o = 16; o; o >>= 1) {
        s0 += __shfl_down_sync(0xffffffffu, s0, o);
        s1 += __shfl_down_sync(0xffffffffu, s1, o);
        s2 += __shfl_down_sync(0xffffffffu, s2, o);
        s3 += __shfl_down_sync(0xffffffffu, s3, o);
    }
    if (lane == 0) { red[0][w] = s0; red[1][w] = s1; red[2][w] = s2; red[3][w] = s3; }
    __syncthreads();
    if (threadIdx.x < 4) {
        float ss = 0.f;
#pragma unroll
        for (int i = 0; i < 8; i++) ss += red[threadIdx.x][i];
        atomicAdd(&g_sum[threadIdx.x], ss);
    }
}

// ---------------- K5: finalize softmax denominators ----------------
__global__ void finalize_kernel() {
    int t = threadIdx.x;
    if (t < NHEADS) {
        g_inv[t] = 1.0f / g_sum[t];
        g_maxf[t] = decf(g_max_u[t]);
    }
}

// ---------------- K6a/b/c: exclusive scan of g_cnt -> g_base ----------------
__global__ void scan1_kernel() {
    __shared__ int sd[256];
    int t = threadIdx.x;
    int idx = blockIdx.x * 256 + t;
    int v = (idx < NNODES) ? g_cnt[idx] : 0;
    sd[t] = v; __syncthreads();
#pragma unroll
    for (int off = 1; off < 256; off <<= 1) {
        int x = (t >= off) ? sd[t - off] : 0;
        __syncthreads();
        sd[t] += x;
        __syncthreads();
    }
    if (idx < NNODES) g_base[idx] = sd[t] - v;
    if (t == 255) g_part[blockIdx.x] = sd[255];
}
__global__ void scan2_kernel() {
    __shared__ int sd[512];
    int t = threadIdx.x;
    int v = (t < SCAN_B) ? g_part[t] : 0;
    sd[t] = v; __syncthreads();
#pragma unroll
    for (int off = 1; off < 512; off <<= 1) {
        int x = (t >= off) ? sd[t - off] : 0;
        __syncthreads();
        sd[t] += x;
        __syncthreads();
    }
    if (t < SCAN_B) g_poff[t] = sd[t] - v;
    if (t == 0) g_base[NNODES] = NEDGES;
}
__global__ void scan3_kernel() {
    int idx = blockIdx.x * 256 + threadIdx.x;
    if (idx < NNODES) g_base[idx] += g_poff[blockIdx.x];
}

// ---------------- K7: place edges into dst-sorted order, materialize attn ----------------
__global__ void place_kernel(const int* __restrict__ ei) {
    const int* src = ei;
    const int* dst = ei + NEDGES;
    float m0 = g_maxf[0], m1 = g_maxf[1], m2 = g_maxf[2], m3 = g_maxf[3];
    float i0 = g_inv[0], i1 = g_inv[1], i2 = g_inv[2], i3 = g_inv[3];
    int stride = gridDim.x * blockDim.x;
    for (int e = blockIdx.x * blockDim.x + threadIdx.x; e < NEDGES; e += stride) {
        int d = dst[e];
        int pos = g_base[d] + atomicAdd(&g_cnt2[d], 1);
        float4 l = *(const float4*)(g_logits + (size_t)e * 4);
        float4 a;
        a.x = __expf(l.x - m0) * i0;
        a.y = __expf(l.y - m1) * i1;
        a.z = __expf(l.z - m2) * i2;
        a.w = __expf(l.w - m3) * i3;
        g_esrc[pos] = src[e];
        g_ea[pos] = a;
    }
}

// ---------------- K8: warp-per-dst aggregation, out = h + agg ----------------
__global__ void agg_kernel(float* __restrict__ out) {
    int lane = threadIdx.x & 31;
    int w = (blockIdx.x * blockDim.x + threadIdx.x) >> 5;
    int nw = (gridDim.x * blockDim.x) >> 5;
    for (int d = w; d < NNODES; d += nw) {
        int beg = g_base[d], end = g_base[d + 1];
        float a0 = 0.f, a1 = 0.f, a2 = 0.f, a3 = 0.f;
        for (int p = beg; p < end; p++) {
            int s = g_esrc[p];            // broadcast
            float4 a = g_ea[p];           // broadcast
            float sv = g_h[(size_t)s * DIM + lane];  // 128B coalesced gather
            a0 = fmaf(a.x, sv, a0);
            a1 = fmaf(a.y, sv, a1);
            a2 = fmaf(a.z, sv, a2);
            a3 = fmaf(a.w, sv, a3);
        }
        const float* hr = g_h + (size_t)d * DIM;
        float* o = out + (size_t)d * DIM;
        o[lane]      = hr[lane]      + a0;
        o[32 + lane] = hr[32 + lane] + a1;
        o[64 + lane] = hr[64 + lane] + a2;
        o[96 + lane] = hr[96 + lane] + a3;
    }
}

// ---------------- launch ----------------
extern "C" void kernel_launch(void* const* d_in, const int* in_sizes, int n_in,
                              void* d_out, int out_size) {
    const float* feat = (const float*)d_in[0];
    const int*   ei   = (const int*)d_in[1];
    const float* Wlin = (const float*)d_in[2];
    const float* blin = (const float*)d_in[3];
    const float* Watt = (const float*)d_in[4];
    const float* batt = (const float*)d_in[5];
    float* out = (float*)d_out;

    zero_kernel<<<(NNODES + 1023) / 1024, 1024>>>();
    va_kernel<<<1, 1024>>>(Wlin, blin, Watt, batt);

    size_t smem = (size_t)(DIM * DIM + DIM + 64 * 132) * sizeof(float);
    cudaFuncSetAttribute(gemm_kernel, cudaFuncAttributeMaxDynamicSharedMemorySize, (int)smem);
    gemm_kernel<<<592, 256, smem>>>(feat, Wlin, blin);

    alpha_kernel<<<592, 256>>>(feat);
    logits_hist_kernel<<<296, 256>>>(ei);
    sum_kernel<<<296, 256>>>();
    finalize_kernel<<<1, 32>>>();
    scan1_kernel<<<SCAN_B, 256>>>();
    scan2_kernel<<<1, 512>>>();
    scan3_kernel<<<SCAN_B, 256>>>();
    place_kernel<<<296, 256>>>(ei);
    agg_kernel<<<1184, 256>>>(out);
}

// round 6
// speedup vs baseline: 2.5333x; 1.5819x over previous
#include <cuda_runtime.h>
#include <cuda_bf16.h>
#include <cstdint>

#define NNODES 100000
#define NEDGES 500000
#define DIM 128
#define NHEADS 4
#define NTILES ((NNODES + 127) / 128)      // 782
#define SCAN_B ((NNODES + 255) / 256)      // 391

// ---------------- scratch ----------------
__device__ float  g_h[NNODES * DIM];           // 51.2 MB
__device__ float  g_asrc[NNODES * NHEADS];
__device__ float  g_adst[NNODES * NHEADS];
__device__ float  g_logits[NEDGES * NHEADS];   // 8 MB
__device__ float  g_va[8 * DIM];               // wa @ W (4 src rows, 4 dst rows)
__device__ float  g_vc[8];                     // b·wa (+ba for dst part)
__device__ float  g_sum[NHEADS];
__device__ float  g_inv[NHEADS];
// counting-sort scratch
__device__ int    g_cnt[NNODES];
__device__ int    g_cnt2[NNODES];
__device__ int    g_base[NNODES + 1];
__device__ int    g_part[SCAN_B];
__device__ int    g_poff[SCAN_B];
__device__ int    g_esrc[NEDGES];
__device__ float4 g_ea[NEDGES];

// ---------------- helpers ----------------
__device__ __forceinline__ uint32_t smaddr(const void* p) {
    return (uint32_t)__cvta_generic_to_shared(p);
}
__device__ __forceinline__ uint32_t pack_bf(__nv_bfloat16 a, __nv_bfloat16 b) {
    unsigned short ua = *(unsigned short*)&a, ub = *(unsigned short*)&b;
    return (uint32_t)ua | ((uint32_t)ub << 16);
}
// swizzled element offset within a [rows][128] bf16 tile (16B chunk xor swizzle)
__device__ __forceinline__ int swz(int row, int ch) {
    return row * 128 + ((ch ^ (row & 7)) << 3);
}

#define LDSM4(r0, r1, r2, r3, addr) \
    asm volatile("ldmatrix.sync.aligned.m8n8.x4.shared.b16 {%0,%1,%2,%3}, [%4];" \
                 : "=r"(r0), "=r"(r1), "=r"(r2), "=r"(r3) : "r"(addr))
#define LDSM2(r0, r1, addr) \
    asm volatile("ldmatrix.sync.aligned.m8n8.x2.shared.b16 {%0,%1}, [%2];" \
                 : "=r"(r0), "=r"(r1) : "r"(addr))
#define MMA16816(d, a, b0, b1) \
    asm volatile("mma.sync.aligned.m16n8k16.row.col.f32.bf16.bf16.f32 " \
                 "{%0,%1,%2,%3}, {%4,%5,%6,%7}, {%8,%9}, {%0,%1,%2,%3};" \
                 : "+f"(d[0]), "+f"(d[1]), "+f"(d[2]), "+f"(d[3]) \
                 : "r"(a[0]), "r"(a[1]), "r"(a[2]), "r"(a[3]), "r"(b0), "r"(b1))

// ---------------- K0: zero counters ----------------
__global__ void zero_kernel() {
    int i = blockIdx.x * blockDim.x + threadIdx.x;
    if (i < NNODES) { g_cnt[i] = 0; g_cnt2[i] = 0; }
    if (i < NHEADS) g_sum[i] = 0.0f;
}

// ---------------- K0b: va = wa @ W, vc = b·wa (+ba) ----------------
__global__ void va_kernel(const float* __restrict__ W,
                          const float* __restrict__ b,
                          const float* __restrict__ Wa,
                          const float* __restrict__ ba) {
    int t = threadIdx.x;               // 1024 threads
    int j = t >> 7, i = t & 127;
    int head = j & 3, part = j >> 2;
    const float* war = Wa + head * 2 * DIM + part * DIM;
    float s = 0.f;
    for (int k = 0; k < DIM; k++) s += war[k] * W[k * DIM + i];
    g_va[j * DIM + i] = s;
    if (t < 8) {
        int hh = t & 3, pp = t >> 2;
        const float* wr = Wa + hh * 2 * DIM + pp * DIM;
        float c = 0.f;
        for (int k = 0; k < DIM; k++) c += b[k] * wr[k];
        if (pp) c += ba[hh];
        g_vc[t] = c;
    }
}

// ---------------- K1: split-bf16 tensor-core GEMM ----------------
// C[128 x 144] = feat_tile[128 x 128] @ [W^T | va^T | pad]  (+bias / vc)
// cols 0..127 -> g_h, 128..135 -> alphas, 136..143 discarded.
// 256 threads = 8 warps as 4(M=32) x 2(N=72).
__global__ void __launch_bounds__(256, 1)
gemm_kernel(const float* __restrict__ feat,
            const float* __restrict__ W,
            const float* __restrict__ b) {
    extern __shared__ char smraw[];
    __nv_bfloat16* Ahi = (__nv_bfloat16*)smraw;          // 128*128
    __nv_bfloat16* Alo = Ahi + 128 * 128;
    __nv_bfloat16* Bhi = Alo + 128 * 128;                // 144*128
    __nv_bfloat16* Blo = Bhi + 144 * 128;
    float* sbias = (float*)(Blo + 144 * 128);            // 144

    int tid = threadIdx.x;

    // ---- stage B (W rows 0..127, va rows 128..135, zeros 136..143) ----
    for (int idx = tid; idx < 144 * 16; idx += 256) {
        int row = idx >> 4, ch = idx & 15;
        float v[8];
        if (row < 128) {
            const float4* p = (const float4*)(W + row * 128 + ch * 8);
            float4 a = p[0], c = p[1];
            v[0] = a.x; v[1] = a.y; v[2] = a.z; v[3] = a.w;
            v[4] = c.x; v[5] = c.y; v[6] = c.z; v[7] = c.w;
        } else if (row < 136) {
            const float4* p = (const float4*)(g_va + (row - 128) * 128 + ch * 8);
            float4 a = p[0], c = p[1];
            v[0] = a.x; v[1] = a.y; v[2] = a.z; v[3] = a.w;
            v[4] = c.x; v[5] = c.y; v[6] = c.z; v[7] = c.w;
        } else {
#pragma unroll
            for (int i = 0; i < 8; i++) v[i] = 0.f;
        }
        uint32_t uh[4], ul[4];
#pragma unroll
        for (int i = 0; i < 4; i++) {
            __nv_bfloat16 h0 = __float2bfloat16(v[2 * i]);
            __nv_bfloat16 h1 = __float2bfloat16(v[2 * i + 1]);
            __nv_bfloat16 l0 = __float2bfloat16(v[2 * i] - __bfloat162float(h0));
            __nv_bfloat16 l1 = __float2bfloat16(v[2 * i + 1] - __bfloat162float(h1));
            uh[i] = pack_bf(h0, h1);
            ul[i] = pack_bf(l0, l1);
        }
        int off = swz(row, ch);
        *(uint4*)(Bhi + off) = make_uint4(uh[0], uh[1], uh[2], uh[3]);
        *(uint4*)(Blo + off) = make_uint4(ul[0], ul[1], ul[2], ul[3]);
    }
    for (int i = tid; i < 144; i += 256)
        sbias[i] = (i < 128) ? b[i] : (i < 136 ? g_vc[i - 128] : 0.f);

    // ---- stage A tile (this block's 128 nodes) ----
    int nb = blockIdx.x * 128;
    for (int idx = tid; idx < 128 * 16; idx += 256) {
        int row = idx >> 4, ch = idx & 15;
        int node = nb + row;
        float v[8];
        if (node < NNODES) {
            const float4* p = (const float4*)(feat + (size_t)node * 128 + ch * 8);
            float4 a = p[0], c = p[1];
            v[0] = a.x; v[1] = a.y; v[2] = a.z; v[3] = a.w;
            v[4] = c.x; v[5] = c.y; v[6] = c.z; v[7] = c.w;
        } else {
#pragma unroll
            for (int i = 0; i < 8; i++) v[i] = 0.f;
        }
        uint32_t uh[4], ul[4];
#pragma unroll
        for (int i = 0; i < 4; i++) {
            __nv_bfloat16 h0 = __float2bfloat16(v[2 * i]);
            __nv_bfloat16 h1 = __float2bfloat16(v[2 * i + 1]);
            __nv_bfloat16 l0 = __float2bfloat16(v[2 * i] - __bfloat162float(h0));
            __nv_bfloat16 l1 = __float2bfloat16(v[2 * i + 1] - __bfloat162float(h1));
            uh[i] = pack_bf(h0, h1);
            ul[i] = pack_bf(l0, l1);
        }
        int off = swz(row, ch);
        *(uint4*)(Ahi + off) = make_uint4(uh[0], uh[1], uh[2], uh[3]);
        *(uint4*)(Alo + off) = make_uint4(ul[0], ul[1], ul[2], ul[3]);
    }
    __syncthreads();

    int warp = tid >> 5, lane = tid & 31;
    int wm = warp & 3, wn = warp >> 2;      // wm: 32-row band, wn: 72-col band

    float acc[2][9][4];
#pragma unroll
    for (int mt = 0; mt < 2; mt++)
#pragma unroll
        for (int nt = 0; nt < 9; nt++)
#pragma unroll
            for (int i = 0; i < 4; i++) acc[mt][nt][i] = 0.f;

    for (int ks = 0; ks < 8; ks++) {
        // A fragments (hi & lo) for 2 m16 tiles
        uint32_t ah[2][4], al[2][4];
#pragma unroll
        for (int mt = 0; mt < 2; mt++) {
            int row = wm * 32 + mt * 16 + (lane & 15);
            int ch = ks * 2 + (lane >> 4);
            uint32_t ad = smaddr(Ahi + swz(row, ch));
            LDSM4(ah[mt][0], ah[mt][1], ah[mt][2], ah[mt][3], ad);
            uint32_t ad2 = smaddr(Alo + swz(row, ch));
            LDSM4(al[mt][0], al[mt][1], al[mt][2], al[mt][3], ad2);
        }
        // 4 pairs of n8 tiles via x4
        int rowb_pair = (lane & 7) + ((lane >> 4) << 3);
        int chb = ks * 2 + ((lane >> 3) & 1);
#pragma unroll
        for (int np = 0; np < 4; np++) {
            int rb = wn * 72 + np * 16 + rowb_pair;
            uint32_t bh[4], bl[4];
            uint32_t bd = smaddr(Bhi + swz(rb, chb));
            LDSM4(bh[0], bh[1], bh[2], bh[3], bd);
            uint32_t bd2 = smaddr(Blo + swz(rb, chb));
            LDSM4(bl[0], bl[1], bl[2], bl[3], bd2);
            int n0 = 2 * np, n1 = 2 * np + 1;
            // pass hi*hi
            MMA16816(acc[0][n0], ah[0], bh[0], bh[1]);
            MMA16816(acc[0][n1], ah[0], bh[2], bh[3]);
            MMA16816(acc[1][n0], ah[1], bh[0], bh[1]);
            MMA16816(acc[1][n1], ah[1], bh[2], bh[3]);
            // pass hi*lo
            MMA16816(acc[0][n0], ah[0], bl[0], bl[1]);
            MMA16816(acc[0][n1], ah[0], bl[2], bl[3]);
            MMA16816(acc[1][n0], ah[1], bl[0], bl[1]);
            MMA16816(acc[1][n1], ah[1], bl[2], bl[3]);
            // pass lo*hi
            MMA16816(acc[0][n0], al[0], bh[0], bh[1]);
            MMA16816(acc[0][n1], al[0], bh[2], bh[3]);
            MMA16816(acc[1][n0], al[1], bh[0], bh[1]);
            MMA16816(acc[1][n1], al[1], bh[2], bh[3]);
        }
        // last n8 tile (nt=8) via x2
        {
            int rb = wn * 72 + 64 + (lane & 7);
            uint32_t b0, b1, c0, c1;
            uint32_t bd = smaddr(Bhi + swz(rb, chb));
            LDSM2(b0, b1, bd);
            uint32_t bd2 = smaddr(Blo + swz(rb, chb));
            LDSM2(c0, c1, bd2);
            MMA16816(acc[0][8], ah[0], b0, b1);
            MMA16816(acc[1][8], ah[1], b0, b1);
            MMA16816(acc[0][8], ah[0], c0, c1);
            MMA16816(acc[1][8], ah[1], c0, c1);
            MMA16816(acc[0][8], al[0], b0, b1);
            MMA16816(acc[1][8], al[1], b0, b1);
        }
    }

    // ---- epilogue ----
    int tq = lane >> 2, tr = lane & 3;
#pragma unroll
    for (int mt = 0; mt < 2; mt++) {
#pragma unroll
        for (int nt = 0; nt < 9; nt++) {
            int col = wn * 72 + nt * 8 + tr * 2;
            if (col >= 136) continue;
            float b0 = sbias[col], b1 = sbias[col + 1];
#pragma unroll
            for (int half = 0; half < 2; half++) {
                int node = nb + wm * 32 + mt * 16 + tq + half * 8;
                if (node >= NNODES) continue;
                float v0 = acc[mt][nt][half * 2] + b0;
                float v1 = acc[mt][nt][half * 2 + 1] + b1;
                if (col < 128) {
                    float2 o; o.x = v0; o.y = v1;
                    *(float2*)(g_h + (size_t)node * DIM + col) = o;
                } else {
                    int j = col - 128;        // even: 0,2,4,6
                    if (j < 4) {
                        g_asrc[node * NHEADS + j] = v0;
                        g_asrc[node * NHEADS + j + 1] = v1;
                    } else {
                        g_adst[node * NHEADS + j - 4] = v0;
                        g_adst[node * NHEADS + j - 3] = v1;
                    }
                }
            }
        }
    }
}

// ---------------- K2: logits + dst histogram + sum(exp) ----------------
__global__ void logits_hist_kernel(const int* __restrict__ ei) {
    const int* src = ei;
    const int* dst = ei + NEDGES;
    float s0 = 0.f, s1 = 0.f, s2 = 0.f, s3 = 0.f;
    int stride = gridDim.x * blockDim.x;
    for (int e = blockIdx.x * blockDim.x + threadIdx.x; e < NEDGES; e += stride) {
        int s = src[e], d = dst[e];
        atomicAdd(&g_cnt[d], 1);
        float4 as = *(const float4*)(g_asrc + (size_t)s * 4);
        float4 ad = *(const float4*)(g_adst + (size_t)d * 4);
        float4 l;
        l.x = as.x + ad.x; l.y = as.y + ad.y;
        l.z = as.z + ad.z; l.w = as.w + ad.w;
        *(float4*)(g_logits + (size_t)e * 4) = l;
        s0 += __expf(l.x); s1 += __expf(l.y);
        s2 += __expf(l.z); s3 += __expf(l.w);
    }
    __shared__ float red[4][8];
    int lane = threadIdx.x & 31, w = threadIdx.x >> 5;
#pragma unroll
    for (int o = 16; o; o >>= 1) {
        s0 += __shfl_down_sync(0xffffffffu, s0, o);
        s1 += __shfl_down_sync(0xffffffffu, s1, o);
        s2 += __shfl_down_sync(0xffffffffu, s2, o);
        s3 += __shfl_down_sync(0xffffffffu, s3, o);
    }
    if (lane == 0) { red[0][w] = s0; red[1][w] = s1; red[2][w] = s2; red[3][w] = s3; }
    __syncthreads();
    if (threadIdx.x < 4) {
        float ss = 0.f;
#pragma unroll
        for (int i = 0; i < 8; i++) ss += red[threadIdx.x][i];
        atomicAdd(&g_sum[threadIdx.x], ss);
    }
}

// ---------------- K3: finalize denominators ----------------
__global__ void finalize_kernel() {
    int t = threadIdx.x;
    if (t < NHEADS) g_inv[t] = 1.0f / g_sum[t];
}

// ---------------- K4a/b/c: exclusive scan of g_cnt -> g_base ----------------
__global__ void scan1_kernel() {
    __shared__ int sd[256];
    int t = threadIdx.x;
    int idx = blockIdx.x * 256 + t;
    int v = (idx < NNODES) ? g_cnt[idx] : 0;
    sd[t] = v; __syncthreads();
#pragma unroll
    for (int off = 1; off < 256; off <<= 1) {
        int x = (t >= off) ? sd[t - off] : 0;
        __syncthreads();
        sd[t] += x;
        __syncthreads();
    }
    if (idx < NNODES) g_base[idx] = sd[t] - v;
    if (t == 255) g_part[blockIdx.x] = sd[255];
}
__global__ void scan2_kernel() {
    __shared__ int sd[512];
    int t = threadIdx.x;
    int v = (t < SCAN_B) ? g_part[t] : 0;
    sd[t] = v; __syncthreads();
#pragma unroll
    for (int off = 1; off < 512; off <<= 1) {
        int x = (t >= off) ? sd[t - off] : 0;
        __syncthreads();
        sd[t] += x;
        __syncthreads();
    }
    if (t < SCAN_B) g_poff[t] = sd[t] - v;
    if (t == 0) g_base[NNODES] = NEDGES;
}
__global__ void scan3_kernel() {
    int idx = blockIdx.x * 256 + threadIdx.x;
    if (idx < NNODES) g_base[idx] += g_poff[blockIdx.x];
}

// ---------------- K5: place edges into dst-sorted order ----------------
__global__ void place_kernel(const int* __restrict__ ei) {
    const int* src = ei;
    const int* dst = ei + NEDGES;
    float i0 = g_inv[0], i1 = g_inv[1], i2 = g_inv[2], i3 = g_inv[3];
    int stride = gridDim.x * blockDim.x;
    for (int e = blockIdx.x * blockDim.x + threadIdx.x; e < NEDGES; e += stride) {
        int d = dst[e];
        int pos = g_base[d] + atomicAdd(&g_cnt2[d], 1);
        float4 l = *(const float4*)(g_logits + (size_t)e * 4);
        float4 a;
        a.x = __expf(l.x) * i0;
        a.y = __expf(l.y) * i1;
        a.z = __expf(l.z) * i2;
        a.w = __expf(l.w) * i3;
        g_esrc[pos] = src[e];
        g_ea[pos] = a;
    }
}

// ---------------- K6: warp-per-dst aggregation, out = h + agg ----------------
__global__ void agg_kernel(float* __restrict__ out) {
    int lane = threadIdx.x & 31;
    int w = (blockIdx.x * blockDim.x + threadIdx.x) >> 5;
    int nw = (gridDim.x * blockDim.x) >> 5;
    for (int d = w; d < NNODES; d += nw) {
        int beg = g_base[d], end = g_base[d + 1];
        float a0 = 0.f, a1 = 0.f, a2 = 0.f, a3 = 0.f;
        int p = beg;
        for (; p + 4 <= end; p += 4) {
            int s0 = g_esrc[p], s1 = g_esrc[p + 1], s2 = g_esrc[p + 2], s3 = g_esrc[p + 3];
            float4 w0 = g_ea[p], w1 = g_ea[p + 1], w2 = g_ea[p + 2], w3 = g_ea[p + 3];
            float v0 = g_h[(size_t)s0 * DIM + lane];
            float v1 = g_h[(size_t)s1 * DIM + lane];
            float v2 = g_h[(size_t)s2 * DIM + lane];
            float v3 = g_h[(size_t)s3 * DIM + lane];
            a0 = fmaf(w0.x, v0, fmaf(w1.x, v1, fmaf(w2.x, v2, fmaf(w3.x, v3, a0))));
            a1 = fmaf(w0.y, v0, fmaf(w1.y, v1, fmaf(w2.y, v2, fmaf(w3.y, v3, a1))));
            a2 = fmaf(w0.z, v0, fmaf(w1.z, v1, fmaf(w2.z, v2, fmaf(w3.z, v3, a2))));
            a3 = fmaf(w0.w, v0, fmaf(w1.w, v1, fmaf(w2.w, v2, fmaf(w3.w, v3, a3))));
        }
        for (; p < end; p++) {
            int s = g_esrc[p];
            float4 a = g_ea[p];
            float sv = g_h[(size_t)s * DIM + lane];
            a0 = fmaf(a.x, sv, a0);
            a1 = fmaf(a.y, sv, a1);
            a2 = fmaf(a.z, sv, a2);
            a3 = fmaf(a.w, sv, a3);
        }
        const float* hr = g_h + (size_t)d * DIM;
        float* o = out + (size_t)d * DIM;
        o[lane]      = hr[lane]      + a0;
        o[32 + lane] = hr[32 + lane] + a1;
        o[64 + lane] = hr[64 + lane] + a2;
        o[96 + lane] = hr[96 + lane] + a3;
    }
}

// ---------------- launch ----------------
extern "C" void kernel_launch(void* const* d_in, const int* in_sizes, int n_in,
                              void* d_out, int out_size) {
    const float* feat = (const float*)d_in[0];
    const int*   ei   = (const int*)d_in[1];
    const float* Wlin = (const float*)d_in[2];
    const float* blin = (const float*)d_in[3];
    const float* Watt = (const float*)d_in[4];
    const float* batt = (const float*)d_in[5];
    float* out = (float*)d_out;

    zero_kernel<<<(NNODES + 1023) / 1024, 1024>>>();
    va_kernel<<<1, 1024>>>(Wlin, blin, Watt, batt);

    // smem: A(hi+lo) 64KB + B(hi+lo) 72KB + bias
    size_t smem = (size_t)(2 * 128 * 128 + 2 * 144 * 128) * sizeof(__nv_bfloat16)
                + 144 * sizeof(float);
    cudaFuncSetAttribute(gemm_kernel, cudaFuncAttributeMaxDynamicSharedMemorySize, (int)smem);
    gemm_kernel<<<NTILES, 256, smem>>>(feat, Wlin, blin);

    logits_hist_kernel<<<296, 256>>>(ei);
    finalize_kernel<<<1, 32>>>();
    scan1_kernel<<<SCAN_B, 256>>>();
    scan2_kernel<<<1, 512>>>();
    scan3_kernel<<<SCAN_B, 256>>>();
    place_kernel<<<296, 256>>>(ei);
    agg_kernel<<<1184, 256>>>(out);
}

// round 7
// speedup vs baseline: 2.5358x; 1.0010x over previous
#include <cuda_runtime.h>
#include <cuda_bf16.h>
#include <cstdint>

#define NNODES 100000
#define NEDGES 500000
#define DIM 128
#define NHEADS 4
#define NTILES ((NNODES + 127) / 128)      // 782
#define SCAN_B ((NNODES + 255) / 256)      // 391

// ---------------- scratch ----------------
__device__ float  g_h[NNODES * DIM];           // 51.2 MB
__device__ float  g_asrc[NNODES * NHEADS];
__device__ float  g_adst[NNODES * NHEADS];
__device__ float  g_logits[NEDGES * NHEADS];   // 8 MB
__device__ float  g_va[8 * DIM];               // wa @ W (4 src rows, 4 dst rows)
__device__ float  g_vc[8];                     // b·wa (+ba for dst part)
__device__ float  g_sum[NHEADS];
__device__ float  g_inv[NHEADS];
// pre-split, pre-swizzled B operand (144 rows x 128 cols bf16, hi+lo) + fused bias
__device__ __nv_bfloat16 g_Bhi[144 * 128];
__device__ __nv_bfloat16 g_Blo[144 * 128];
__device__ float  g_bias[144];
// counting-sort scratch
__device__ int    g_cnt[NNODES];
__device__ int    g_cnt2[NNODES];
__device__ int    g_base[NNODES + 1];
__device__ int    g_part[SCAN_B];
__device__ int    g_poff[SCAN_B];
__device__ int    g_esrc[NEDGES];
__device__ float4 g_ea[NEDGES];

// ---------------- helpers ----------------
__device__ __forceinline__ uint32_t smaddr(const void* p) {
    return (uint32_t)__cvta_generic_to_shared(p);
}
__device__ __forceinline__ uint32_t pack_bf(__nv_bfloat16 a, __nv_bfloat16 b) {
    unsigned short ua = *(unsigned short*)&a, ub = *(unsigned short*)&b;
    return (uint32_t)ua | ((uint32_t)ub << 16);
}
// swizzled element offset within a [rows][128] bf16 tile (16B chunk xor swizzle)
__device__ __forceinline__ int swz(int row, int ch) {
    return row * 128 + ((ch ^ (row & 7)) << 3);
}

#define LDSM4(r0, r1, r2, r3, addr) \
    asm volatile("ldmatrix.sync.aligned.m8n8.x4.shared.b16 {%0,%1,%2,%3}, [%4];" \
                 : "=r"(r0), "=r"(r1), "=r"(r2), "=r"(r3) : "r"(addr))
#define LDSM2(r0, r1, addr) \
    asm volatile("ldmatrix.sync.aligned.m8n8.x2.shared.b16 {%0,%1}, [%2];" \
                 : "=r"(r0), "=r"(r1) : "r"(addr))
#define MMA16816(d, a, b0, b1) \
    asm volatile("mma.sync.aligned.m16n8k16.row.col.f32.bf16.bf16.f32 " \
                 "{%0,%1,%2,%3}, {%4,%5,%6,%7}, {%8,%9}, {%0,%1,%2,%3};" \
                 : "+f"(d[0]), "+f"(d[1]), "+f"(d[2]), "+f"(d[3]) \
                 : "r"(a[0]), "r"(a[1]), "r"(a[2]), "r"(a[3]), "r"(b0), "r"(b1))

// ---------------- K0: zero counters ----------------
__global__ void zero_kernel() {
    int i = blockIdx.x * blockDim.x + threadIdx.x;
    if (i < NNODES) { g_cnt[i] = 0; g_cnt2[i] = 0; }
    if (i < NHEADS) g_sum[i] = 0.0f;
}

// ---------------- K0b: va = wa @ W, vc = b·wa (+ba) ----------------
__global__ void va_kernel(const float* __restrict__ W,
                          const float* __restrict__ b,
                          const float* __restrict__ Wa,
                          const float* __restrict__ ba) {
    int t = threadIdx.x;               // 1024 threads
    int j = t >> 7, i = t & 127;
    int head = j & 3, part = j >> 2;
    const float* war = Wa + head * 2 * DIM + part * DIM;
    float s = 0.f;
    for (int k = 0; k < DIM; k++) s += war[k] * W[k * DIM + i];
    g_va[j * DIM + i] = s;
    if (t < 8) {
        int hh = t & 3, pp = t >> 2;
        const float* wr = Wa + hh * 2 * DIM + pp * DIM;
        float c = 0.f;
        for (int k = 0; k < DIM; k++) c += b[k] * wr[k];
        if (pp) c += ba[hh];
        g_vc[t] = c;
    }
}

// ---------------- K0c: pre-split + pre-swizzle B, fuse bias ----------------
// B rows: 0..127 = W, 128..135 = va, 136..143 = zeros. Stored in swz layout.
__global__ void splitB_kernel(const float* __restrict__ W,
                              const float* __restrict__ b) {
    int idx = blockIdx.x * blockDim.x + threadIdx.x;   // 144*16 items
    if (idx >= 144 * 16) return;
    int row = idx >> 4, ch = idx & 15;
    float v[8];
    if (row < 128) {
        const float4* p = (const float4*)(W + row * 128 + ch * 8);
        float4 a = p[0], c = p[1];
        v[0] = a.x; v[1] = a.y; v[2] = a.z; v[3] = a.w;
        v[4] = c.x; v[5] = c.y; v[6] = c.z; v[7] = c.w;
    } else if (row < 136) {
        const float4* p = (const float4*)(g_va + (row - 128) * 128 + ch * 8);
        float4 a = p[0], c = p[1];
        v[0] = a.x; v[1] = a.y; v[2] = a.z; v[3] = a.w;
        v[4] = c.x; v[5] = c.y; v[6] = c.z; v[7] = c.w;
    } else {
#pragma unroll
        for (int i = 0; i < 8; i++) v[i] = 0.f;
    }
    uint32_t uh[4], ul[4];
#pragma unroll
    for (int i = 0; i < 4; i++) {
        __nv_bfloat16 h0 = __float2bfloat16(v[2 * i]);
        __nv_bfloat16 h1 = __float2bfloat16(v[2 * i + 1]);
        __nv_bfloat16 l0 = __float2bfloat16(v[2 * i] - __bfloat162float(h0));
        __nv_bfloat16 l1 = __float2bfloat16(v[2 * i + 1] - __bfloat162float(h1));
        uh[i] = pack_bf(h0, h1);
        ul[i] = pack_bf(l0, l1);
    }
    int off = swz(row, ch);
    *(uint4*)(g_Bhi + off) = make_uint4(uh[0], uh[1], uh[2], uh[3]);
    *(uint4*)(g_Blo + off) = make_uint4(ul[0], ul[1], ul[2], ul[3]);
    if (idx < 144)
        g_bias[idx] = (idx < 128) ? b[idx] : (idx < 136 ? g_vc[idx - 128] : 0.f);
}

// ---------------- K1: split-bf16 tensor-core GEMM ----------------
// C[128 x 144] = feat_tile[128 x 128] @ [W^T | va^T | pad]  (+bias / vc)
// cols 0..127 -> g_h, 128..135 -> alphas. 256 threads = 8 warps, 4(M) x 2(N).
__global__ void __launch_bounds__(256, 1)
gemm_kernel(const float* __restrict__ feat) {
    extern __shared__ char smraw[];
    __nv_bfloat16* Ahi = (__nv_bfloat16*)smraw;          // 128*128
    __nv_bfloat16* Alo = Ahi + 128 * 128;
    __nv_bfloat16* Bhi = Alo + 128 * 128;                // 144*128
    __nv_bfloat16* Blo = Bhi + 144 * 128;
    float* sbias = (float*)(Blo + 144 * 128);            // 144

    int tid = threadIdx.x;

    // ---- stage B: plain vector copies (pre-split, pre-swizzled) ----
    for (int i = tid; i < 144 * 128 / 8; i += 256) {
        ((uint4*)Bhi)[i] = ((const uint4*)g_Bhi)[i];
        ((uint4*)Blo)[i] = ((const uint4*)g_Blo)[i];
    }
    for (int i = tid; i < 144; i += 256) sbias[i] = g_bias[i];

    // ---- stage A tile (this block's 128 nodes): convert fp32 -> hi/lo bf16 ----
    int nb = blockIdx.x * 128;
    for (int idx = tid; idx < 128 * 16; idx += 256) {
        int row = idx >> 4, ch = idx & 15;
        int node = nb + row;
        float v[8];
        if (node < NNODES) {
            const float4* p = (const float4*)(feat + (size_t)node * 128 + ch * 8);
            float4 a = p[0], c = p[1];
            v[0] = a.x; v[1] = a.y; v[2] = a.z; v[3] = a.w;
            v[4] = c.x; v[5] = c.y; v[6] = c.z; v[7] = c.w;
        } else {
#pragma unroll
            for (int i = 0; i < 8; i++) v[i] = 0.f;
        }
        uint32_t uh[4], ul[4];
#pragma unroll
        for (int i = 0; i < 4; i++) {
            __nv_bfloat16 h0 = __float2bfloat16(v[2 * i]);
            __nv_bfloat16 h1 = __float2bfloat16(v[2 * i + 1]);
            __nv_bfloat16 l0 = __float2bfloat16(v[2 * i] - __bfloat162float(h0));
            __nv_bfloat16 l1 = __float2bfloat16(v[2 * i + 1] - __bfloat162float(h1));
            uh[i] = pack_bf(h0, h1);
            ul[i] = pack_bf(l0, l1);
        }
        int off = swz(row, ch);
        *(uint4*)(Ahi + off) = make_uint4(uh[0], uh[1], uh[2], uh[3]);
        *(uint4*)(Alo + off) = make_uint4(ul[0], ul[1], ul[2], ul[3]);
    }
    __syncthreads();

    int warp = tid >> 5, lane = tid & 31;
    int wm = warp & 3, wn = warp >> 2;      // wm: 32-row band, wn: 72-col band

    float acc[2][9][4];
#pragma unroll
    for (int mt = 0; mt < 2; mt++)
#pragma unroll
        for (int nt = 0; nt < 9; nt++)
#pragma unroll
            for (int i = 0; i < 4; i++) acc[mt][nt][i] = 0.f;

    for (int ks = 0; ks < 8; ks++) {
        uint32_t ah[2][4], al[2][4];
#pragma unroll
        for (int mt = 0; mt < 2; mt++) {
            int row = wm * 32 + mt * 16 + (lane & 15);
            int ch = ks * 2 + (lane >> 4);
            uint32_t ad = smaddr(Ahi + swz(row, ch));
            LDSM4(ah[mt][0], ah[mt][1], ah[mt][2], ah[mt][3], ad);
            uint32_t ad2 = smaddr(Alo + swz(row, ch));
            LDSM4(al[mt][0], al[mt][1], al[mt][2], al[mt][3], ad2);
        }
        int rowb_pair = (lane & 7) + ((lane >> 4) << 3);
        int chb = ks * 2 + ((lane >> 3) & 1);
#pragma unroll
        for (int np = 0; np < 4; np++) {
            int rb = wn * 72 + np * 16 + rowb_pair;
            uint32_t bh[4], bl[4];
            uint32_t bd = smaddr(Bhi + swz(rb, chb));
            LDSM4(bh[0], bh[1], bh[2], bh[3], bd);
            uint32_t bd2 = smaddr(Blo + swz(rb, chb));
            LDSM4(bl[0], bl[1], bl[2], bl[3], bd2);
            int n0 = 2 * np, n1 = 2 * np + 1;
            MMA16816(acc[0][n0], ah[0], bh[0], bh[1]);
            MMA16816(acc[0][n1], ah[0], bh[2], bh[3]);
            MMA16816(acc[1][n0], ah[1], bh[0], bh[1]);
            MMA16816(acc[1][n1], ah[1], bh[2], bh[3]);
            MMA16816(acc[0][n0], ah[0], bl[0], bl[1]);
            MMA16816(acc[0][n1], ah[0], bl[2], bl[3]);
            MMA16816(acc[1][n0], ah[1], bl[0], bl[1]);
            MMA16816(acc[1][n1], ah[1], bl[2], bl[3]);
            MMA16816(acc[0][n0], al[0], bh[0], bh[1]);
            MMA16816(acc[0][n1], al[0], bh[2], bh[3]);
            MMA16816(acc[1][n0], al[1], bh[0], bh[1]);
            MMA16816(acc[1][n1], al[1], bh[2], bh[3]);
        }
        {
            int rb = wn * 72 + 64 + (lane & 7);
            uint32_t b0, b1, c0, c1;
            uint32_t bd = smaddr(Bhi + swz(rb, chb));
            LDSM2(b0, b1, bd);
            uint32_t bd2 = smaddr(Blo + swz(rb, chb));
            LDSM2(c0, c1, bd2);
            MMA16816(acc[0][8], ah[0], b0, b1);
            MMA16816(acc[1][8], ah[1], b0, b1);
            MMA16816(acc[0][8], ah[0], c0, c1);
            MMA16816(acc[1][8], ah[1], c0, c1);
            MMA16816(acc[0][8], al[0], b0, b1);
            MMA16816(acc[1][8], al[1], b0, b1);
        }
    }

    // ---- epilogue ----
    int tq = lane >> 2, tr = lane & 3;
#pragma unroll
    for (int mt = 0; mt < 2; mt++) {
#pragma unroll
        for (int nt = 0; nt < 9; nt++) {
            int col = wn * 72 + nt * 8 + tr * 2;
            if (col >= 136) continue;
            float b0 = sbias[col], b1 = sbias[col + 1];
#pragma unroll
            for (int half = 0; half < 2; half++) {
                int node = nb + wm * 32 + mt * 16 + tq + half * 8;
                if (node >= NNODES) continue;
                float v0 = acc[mt][nt][half * 2] + b0;
                float v1 = acc[mt][nt][half * 2 + 1] + b1;
                if (col < 128) {
                    float2 o; o.x = v0; o.y = v1;
                    *(float2*)(g_h + (size_t)node * DIM + col) = o;
                } else {
                    int j = col - 128;        // even: 0,2,4,6
                    if (j < 4) {
                        g_asrc[node * NHEADS + j] = v0;
                        g_asrc[node * NHEADS + j + 1] = v1;
                    } else {
                        g_adst[node * NHEADS + j - 4] = v0;
                        g_adst[node * NHEADS + j - 3] = v1;
                    }
                }
            }
        }
    }
}

// ---------------- K2: logits + dst histogram + sum(exp) ----------------
__global__ void logits_hist_kernel(const int* __restrict__ ei) {
    const int* src = ei;
    const int* dst = ei + NEDGES;
    float s0 = 0.f, s1 = 0.f, s2 = 0.f, s3 = 0.f;
    int stride = gridDim.x * blockDim.x;
    for (int e = blockIdx.x * blockDim.x + threadIdx.x; e < NEDGES; e += stride) {
        int s = src[e], d = dst[e];
        atomicAdd(&g_cnt[d], 1);
        float4 as = *(const float4*)(g_asrc + (size_t)s * 4);
        float4 ad = *(const float4*)(g_adst + (size_t)d * 4);
        float4 l;
        l.x = as.x + ad.x; l.y = as.y + ad.y;
        l.z = as.z + ad.z; l.w = as.w + ad.w;
        *(float4*)(g_logits + (size_t)e * 4) = l;
        s0 += __expf(l.x); s1 += __expf(l.y);
        s2 += __expf(l.z); s3 += __expf(l.w);
    }
    __shared__ float red[4][8];
    int lane = threadIdx.x & 31, w = threadIdx.x >> 5;
#pragma unroll
    for (int o = 16; o; o >>= 1) {
        s0 += __shfl_down_sync(0xffffffffu, s0, o);
        s1 += __shfl_down_sync(0xffffffffu, s1, o);
        s2 += __shfl_down_sync(0xffffffffu, s2, o);
        s3 += __shfl_down_sync(0xffffffffu, s3, o);
    }
    if (lane == 0) { red[0][w] = s0; red[1][w] = s1; red[2][w] = s2; red[3][w] = s3; }
    __syncthreads();
    if (threadIdx.x < 4) {
        float ss = 0.f;
#pragma unroll
        for (int i = 0; i < 8; i++) ss += red[threadIdx.x][i];
        atomicAdd(&g_sum[threadIdx.x], ss);
    }
}

// ---------------- K4a/b/c: exclusive scan of g_cnt -> g_base ----------------
__global__ void scan1_kernel() {
    __shared__ int sd[256];
    int t = threadIdx.x;
    int idx = blockIdx.x * 256 + t;
    int v = (idx < NNODES) ? g_cnt[idx] : 0;
    sd[t] = v; __syncthreads();
#pragma unroll
    for (int off = 1; off < 256; off <<= 1) {
        int x = (t >= off) ? sd[t - off] : 0;
        __syncthreads();
        sd[t] += x;
        __syncthreads();
    }
    if (idx < NNODES) g_base[idx] = sd[t] - v;
    if (t == 255) g_part[blockIdx.x] = sd[255];
}
__global__ void scan2_kernel() {
    if (threadIdx.x < NHEADS) g_inv[threadIdx.x] = 1.0f / g_sum[threadIdx.x];
    __shared__ int sd[512];
    int t = threadIdx.x;
    int v = (t < SCAN_B) ? g_part[t] : 0;
    sd[t] = v; __syncthreads();
#pragma unroll
    for (int off = 1; off < 512; off <<= 1) {
        int x = (t >= off) ? sd[t - off] : 0;
        __syncthreads();
        sd[t] += x;
        __syncthreads();
    }
    if (t < SCAN_B) g_poff[t] = sd[t] - v;
    if (t == 0) g_base[NNODES] = NEDGES;
}
__global__ void scan3_kernel() {
    int idx = blockIdx.x * 256 + threadIdx.x;
    if (idx < NNODES) g_base[idx] += g_poff[blockIdx.x];
}

// ---------------- K5: place edges into dst-sorted order ----------------
__global__ void place_kernel(const int* __restrict__ ei) {
    const int* src = ei;
    const int* dst = ei + NEDGES;
    float i0 = g_inv[0], i1 = g_inv[1], i2 = g_inv[2], i3 = g_inv[3];
    int stride = gridDim.x * blockDim.x;
    for (int e = blockIdx.x * blockDim.x + threadIdx.x; e < NEDGES; e += stride) {
        int d = dst[e];
        int pos = g_base[d] + atomicAdd(&g_cnt2[d], 1);
        float4 l = *(const float4*)(g_logits + (size_t)e * 4);
        float4 a;
        a.x = __expf(l.x) * i0;
        a.y = __expf(l.y) * i1;
        a.z = __expf(l.z) * i2;
        a.w = __expf(l.w) * i3;
        g_esrc[pos] = src[e];
        g_ea[pos] = a;
    }
}

// ---------------- K6: warp-per-dst aggregation, out = h + agg ----------------
__global__ void agg_kernel(float* __restrict__ out) {
    int lane = threadIdx.x & 31;
    int w = (blockIdx.x * blockDim.x + threadIdx.x) >> 5;
    int nw = (gridDim.x * blockDim.x) >> 5;
    for (int d = w; d < NNODES; d += nw) {
        int beg = g_base[d], end = g_base[d + 1];
        float a0 = 0.f, a1 = 0.f, a2 = 0.f, a3 = 0.f;
        int p = beg;
        for (; p + 4 <= end; p += 4) {
            int s0 = g_esrc[p], s1 = g_esrc[p + 1], s2 = g_esrc[p + 2], s3 = g_esrc[p + 3];
            float4 w0 = g_ea[p], w1 = g_ea[p + 1], w2 = g_ea[p + 2], w3 = g_ea[p + 3];
            float v0 = g_h[(size_t)s0 * DIM + lane];
            float v1 = g_h[(size_t)s1 * DIM + lane];
            float v2 = g_h[(size_t)s2 * DIM + lane];
            float v3 = g_h[(size_t)s3 * DIM + lane];
            a0 = fmaf(w0.x, v0, fmaf(w1.x, v1, fmaf(w2.x, v2, fmaf(w3.x, v3, a0))));
            a1 = fmaf(w0.y, v0, fmaf(w1.y, v1, fmaf(w2.y, v2, fmaf(w3.y, v3, a1))));
            a2 = fmaf(w0.z, v0, fmaf(w1.z, v1, fmaf(w2.z, v2, fmaf(w3.z, v3, a2))));
            a3 = fmaf(w0.w, v0, fmaf(w1.w, v1, fmaf(w2.w, v2, fmaf(w3.w, v3, a3))));
        }
        for (; p < end; p++) {
            int s = g_esrc[p];
            float4 a = g_ea[p];
            float sv = g_h[(size_t)s * DIM + lane];
            a0 = fmaf(a.x, sv, a0);
            a1 = fmaf(a.y, sv, a1);
            a2 = fmaf(a.z, sv, a2);
            a3 = fmaf(a.w, sv, a3);
        }
        const float* hr = g_h + (size_t)d * DIM;
        float* o = out + (size_t)d * DIM;
        o[lane]      = hr[lane]      + a0;
        o[32 + lane] = hr[32 + lane] + a1;
        o[64 + lane] = hr[64 + lane] + a2;
        o[96 + lane] = hr[96 + lane] + a3;
    }
}

// ---------------- launch ----------------
extern "C" void kernel_launch(void* const* d_in, const int* in_sizes, int n_in,
                              void* d_out, int out_size) {
    const float* feat = (const float*)d_in[0];
    const int*   ei   = (const int*)d_in[1];
    const float* Wlin = (const float*)d_in[2];
    const float* blin = (const float*)d_in[3];
    const float* Watt = (const float*)d_in[4];
    const float* batt = (const float*)d_in[5];
    float* out = (float*)d_out;

    zero_kernel<<<(NNODES + 1023) / 1024, 1024>>>();
    va_kernel<<<1, 1024>>>(Wlin, blin, Watt, batt);
    splitB_kernel<<<(144 * 16 + 255) / 256, 256>>>(Wlin, blin);

    size_t smem = (size_t)(2 * 128 * 128 + 2 * 144 * 128) * sizeof(__nv_bfloat16)
                + 144 * sizeof(float);
    cudaFuncSetAttribute(gemm_kernel, cudaFuncAttributeMaxDynamicSharedMemorySize, (int)smem);
    gemm_kernel<<<NTILES, 256, smem>>>(feat);

    logits_hist_kernel<<<1184, 256>>>(ei);
    scan1_kernel<<<SCAN_B, 256>>>();
    scan2_kernel<<<1, 512>>>();
    scan3_kernel<<<SCAN_B, 256>>>();
    place_kernel<<<1184, 256>>>(ei);
    agg_kernel<<<1480, 256>>>(out);
}

// round 8
// speedup vs baseline: 2.6567x; 1.0477x over previous
#include <cuda_runtime.h>
#include <cuda_bf16.h>
#include <cstdint>

#define NNODES 100000
#define NEDGES 500000
#define DIM 128
#define NHEADS 4
#define NTILES ((NNODES + 127) / 128)      // 782
#define SCAN_B ((NNODES + 255) / 256)      // 391

// ---------------- scratch ----------------
__device__ float  g_h[NNODES * DIM];           // 51.2 MB
__device__ float  g_asrc[NNODES * NHEADS];
__device__ float  g_adst[NNODES * NHEADS];
__device__ float  g_logits[NEDGES * NHEADS];   // 8 MB
__device__ float  g_va[8 * DIM];               // wa @ W (4 src rows, 4 dst rows)
__device__ float  g_vc[8];                     // b·wa (+ba for dst part)
__device__ float  g_sum[NHEADS];
__device__ float  g_inv[NHEADS];
// pre-split, pre-swizzled B operand (144 rows x 128 cols bf16, hi+lo) + fused bias
__device__ __nv_bfloat16 g_Bhi[144 * 128];
__device__ __nv_bfloat16 g_Blo[144 * 128];
__device__ float  g_bias[144];
// counting-sort scratch
__device__ int    g_cnt[NNODES];
__device__ int    g_cnt2[NNODES];
__device__ int    g_base[NNODES + 1];
__device__ int    g_part[SCAN_B];
__device__ int    g_poff[SCAN_B];
__device__ int    g_esrc[NEDGES];
__device__ float4 g_ea[NEDGES];

// ---------------- helpers ----------------
__device__ __forceinline__ uint32_t smaddr(const void* p) {
    return (uint32_t)__cvta_generic_to_shared(p);
}
__device__ __forceinline__ uint32_t pack_bf(__nv_bfloat16 a, __nv_bfloat16 b) {
    unsigned short ua = *(unsigned short*)&a, ub = *(unsigned short*)&b;
    return (uint32_t)ua | ((uint32_t)ub << 16);
}
// swizzled element offset within a [rows][128] bf16 tile (16B chunk xor swizzle)
__device__ __forceinline__ int swz(int row, int ch) {
    return row * 128 + ((ch ^ (row & 7)) << 3);
}

#define LDSM4(r0, r1, r2, r3, addr) \
    asm volatile("ldmatrix.sync.aligned.m8n8.x4.shared.b16 {%0,%1,%2,%3}, [%4];" \
                 : "=r"(r0), "=r"(r1), "=r"(r2), "=r"(r3) : "r"(addr))
#define LDSM2(r0, r1, addr) \
    asm volatile("ldmatrix.sync.aligned.m8n8.x2.shared.b16 {%0,%1}, [%2];" \
                 : "=r"(r0), "=r"(r1) : "r"(addr))
#define MMA16816(d, a, b0, b1) \
    asm volatile("mma.sync.aligned.m16n8k16.row.col.f32.bf16.bf16.f32 " \
                 "{%0,%1,%2,%3}, {%4,%5,%6,%7}, {%8,%9}, {%0,%1,%2,%3};" \
                 : "+f"(d[0]), "+f"(d[1]), "+f"(d[2]), "+f"(d[3]) \
                 : "r"(a[0]), "r"(a[1]), "r"(a[2]), "r"(a[3]), "r"(b0), "r"(b1))

// ---------------- K0: zero counters ----------------
__global__ void zero_kernel() {
    int i = blockIdx.x * blockDim.x + threadIdx.x;
    if (i < NNODES) { g_cnt[i] = 0; g_cnt2[i] = 0; }
    if (i < NHEADS) g_sum[i] = 0.0f;
}

// ---------------- K0b: va = wa @ W, vc = b·wa (+ba) ----------------
__global__ void va_kernel(const float* __restrict__ W,
                          const float* __restrict__ b,
                          const float* __restrict__ Wa,
                          const float* __restrict__ ba) {
    int t = threadIdx.x;               // 1024 threads
    int j = t >> 7, i = t & 127;
    int head = j & 3, part = j >> 2;
    const float* war = Wa + head * 2 * DIM + part * DIM;
    float s = 0.f;
    for (int k = 0; k < DIM; k++) s += war[k] * W[k * DIM + i];
    g_va[j * DIM + i] = s;
    if (t < 8) {
        int hh = t & 3, pp = t >> 2;
        const float* wr = Wa + hh * 2 * DIM + pp * DIM;
        float c = 0.f;
        for (int k = 0; k < DIM; k++) c += b[k] * wr[k];
        if (pp) c += ba[hh];
        g_vc[t] = c;
    }
}

// ---------------- K0c: pre-split + pre-swizzle B, fuse bias ----------------
__global__ void splitB_kernel(const float* __restrict__ W,
                              const float* __restrict__ b) {
    int idx = blockIdx.x * blockDim.x + threadIdx.x;   // 144*16 items
    if (idx >= 144 * 16) return;
    int row = idx >> 4, ch = idx & 15;
    float v[8];
    if (row < 128) {
        const float4* p = (const float4*)(W + row * 128 + ch * 8);
        float4 a = p[0], c = p[1];
        v[0] = a.x; v[1] = a.y; v[2] = a.z; v[3] = a.w;
        v[4] = c.x; v[5] = c.y; v[6] = c.z; v[7] = c.w;
    } else if (row < 136) {
        const float4* p = (const float4*)(g_va + (row - 128) * 128 + ch * 8);
        float4 a = p[0], c = p[1];
        v[0] = a.x; v[1] = a.y; v[2] = a.z; v[3] = a.w;
        v[4] = c.x; v[5] = c.y; v[6] = c.z; v[7] = c.w;
    } else {
#pragma unroll
        for (int i = 0; i < 8; i++) v[i] = 0.f;
    }
    uint32_t uh[4], ul[4];
#pragma unroll
    for (int i = 0; i < 4; i++) {
        __nv_bfloat16 h0 = __float2bfloat16(v[2 * i]);
        __nv_bfloat16 h1 = __float2bfloat16(v[2 * i + 1]);
        __nv_bfloat16 l0 = __float2bfloat16(v[2 * i] - __bfloat162float(h0));
        __nv_bfloat16 l1 = __float2bfloat16(v[2 * i + 1] - __bfloat162float(h1));
        uh[i] = pack_bf(h0, h1);
        ul[i] = pack_bf(l0, l1);
    }
    int off = swz(row, ch);
    *(uint4*)(g_Bhi + off) = make_uint4(uh[0], uh[1], uh[2], uh[3]);
    *(uint4*)(g_Blo + off) = make_uint4(ul[0], ul[1], ul[2], ul[3]);
    if (idx < 144)
        g_bias[idx] = (idx < 128) ? b[idx] : (idx < 136 ? g_vc[idx - 128] : 0.f);
}

// ---------------- K1: split-bf16 tensor-core GEMM, N-split for 2 CTAs/SM ----------------
// Block (bx, ny): C[128 x 72] slab, cols [72*ny, 72*ny+72).
// 8 warps, each 1 m16-row band x 9 n8 tiles. ~100KB smem -> 2 CTAs/SM.
__global__ void __launch_bounds__(256)
gemm_kernel(const float* __restrict__ feat) {
    extern __shared__ char smraw[];
    __nv_bfloat16* Ahi = (__nv_bfloat16*)smraw;          // 128*128 (32KB)
    __nv_bfloat16* Alo = Ahi + 128 * 128;                // 32KB
    __nv_bfloat16* Bhi = Alo + 128 * 128;                // 72*128 (18KB)
    __nv_bfloat16* Blo = Bhi + 72 * 128;                 // 18KB
    float* sbias = (float*)(Blo + 72 * 128);             // 72

    int tid = threadIdx.x;
    int ny = blockIdx.y;
    int col_base = ny * 72;     // 72 = 8*9, 8-aligned: swizzle slice stays valid

    // ---- stage B: contiguous pre-swizzled slice ----
    {
        const uint4* srcH = (const uint4*)(g_Bhi + col_base * 128);
        const uint4* srcL = (const uint4*)(g_Blo + col_base * 128);
        for (int i = tid; i < 72 * 128 / 8; i += 256) {
            ((uint4*)Bhi)[i] = srcH[i];
            ((uint4*)Blo)[i] = srcL[i];
        }
        for (int i = tid; i < 72; i += 256) sbias[i] = g_bias[col_base + i];
    }

    // ---- stage A tile: fp32 -> hi/lo bf16 split ----
    int nb = blockIdx.x * 128;
    for (int idx = tid; idx < 128 * 16; idx += 256) {
        int row = idx >> 4, ch = idx & 15;
        int node = nb + row;
        float v[8];
        if (node < NNODES) {
            const float4* p = (const float4*)(feat + (size_t)node * 128 + ch * 8);
            float4 a = p[0], c = p[1];
            v[0] = a.x; v[1] = a.y; v[2] = a.z; v[3] = a.w;
            v[4] = c.x; v[5] = c.y; v[6] = c.z; v[7] = c.w;
        } else {
#pragma unroll
            for (int i = 0; i < 8; i++) v[i] = 0.f;
        }
        uint32_t uh[4], ul[4];
#pragma unroll
        for (int i = 0; i < 4; i++) {
            __nv_bfloat16 h0 = __float2bfloat16(v[2 * i]);
            __nv_bfloat16 h1 = __float2bfloat16(v[2 * i + 1]);
            __nv_bfloat16 l0 = __float2bfloat16(v[2 * i] - __bfloat162float(h0));
            __nv_bfloat16 l1 = __float2bfloat16(v[2 * i + 1] - __bfloat162float(h1));
            uh[i] = pack_bf(h0, h1);
            ul[i] = pack_bf(l0, l1);
        }
        int off = swz(row, ch);
        *(uint4*)(Ahi + off) = make_uint4(uh[0], uh[1], uh[2], uh[3]);
        *(uint4*)(Alo + off) = make_uint4(ul[0], ul[1], ul[2], ul[3]);
    }
    __syncthreads();

    int warp = tid >> 5, lane = tid & 31;   // warp = m16 band

    float acc[9][4];
#pragma unroll
    for (int nt = 0; nt < 9; nt++)
#pragma unroll
        for (int i = 0; i < 4; i++) acc[nt][i] = 0.f;

    for (int ks = 0; ks < 8; ks++) {
        uint32_t ah[4], al[4];
        {
            int row = warp * 16 + (lane & 15);
            int ch = ks * 2 + (lane >> 4);
            uint32_t ad = smaddr(Ahi + swz(row, ch));
            LDSM4(ah[0], ah[1], ah[2], ah[3], ad);
            uint32_t ad2 = smaddr(Alo + swz(row, ch));
            LDSM4(al[0], al[1], al[2], al[3], ad2);
        }
        int rowb_pair = (lane & 7) + ((lane >> 4) << 3);
        int chb = ks * 2 + ((lane >> 3) & 1);
#pragma unroll
        for (int np = 0; np < 4; np++) {
            int rb = np * 16 + rowb_pair;       // local B row
            uint32_t bh[4], bl[4];
            uint32_t bd = smaddr(Bhi + swz(rb, chb));
            LDSM4(bh[0], bh[1], bh[2], bh[3], bd);
            uint32_t bd2 = smaddr(Blo + swz(rb, chb));
            LDSM4(bl[0], bl[1], bl[2], bl[3], bd2);
            int n0 = 2 * np, n1 = 2 * np + 1;
            MMA16816(acc[n0], ah, bh[0], bh[1]);
            MMA16816(acc[n1], ah, bh[2], bh[3]);
            MMA16816(acc[n0], ah, bl[0], bl[1]);
            MMA16816(acc[n1], ah, bl[2], bl[3]);
            MMA16816(acc[n0], al, bh[0], bh[1]);
            MMA16816(acc[n1], al, bh[2], bh[3]);
        }
        {
            int rb = 64 + (lane & 7);
            uint32_t b0, b1, c0, c1;
            uint32_t bd = smaddr(Bhi + swz(rb, chb));
            LDSM2(b0, b1, bd);
            uint32_t bd2 = smaddr(Blo + swz(rb, chb));
            LDSM2(c0, c1, bd2);
            MMA16816(acc[8], ah, b0, b1);
            MMA16816(acc[8], ah, c0, c1);
            MMA16816(acc[8], al, b0, b1);
        }
    }

    // ---- epilogue ----
    int tq = lane >> 2, tr = lane & 3;
#pragma unroll
    for (int nt = 0; nt < 9; nt++) {
        int col = col_base + nt * 8 + tr * 2;
        if (col >= 136) continue;
        float b0 = sbias[col - col_base], b1 = sbias[col - col_base + 1];
#pragma unroll
        for (int half = 0; half < 2; half++) {
            int node = nb + warp * 16 + tq + half * 8;
            if (node >= NNODES) continue;
            float v0 = acc[nt][half * 2] + b0;
            float v1 = acc[nt][half * 2 + 1] + b1;
            if (col < 128) {
                float2 o; o.x = v0; o.y = v1;
                *(float2*)(g_h + (size_t)node * DIM + col) = o;
            } else {
                int j = col - 128;        // even: 0,2,4,6
                if (j < 4) {
                    g_asrc[node * NHEADS + j] = v0;
                    g_asrc[node * NHEADS + j + 1] = v1;
                } else {
                    g_adst[node * NHEADS + j - 4] = v0;
                    g_adst[node * NHEADS + j - 3] = v1;
                }
            }
        }
    }
}

// ---------------- K2: logits + dst histogram + sum(exp) ----------------
__global__ void logits_hist_kernel(const int* __restrict__ ei) {
    const int* src = ei;
    const int* dst = ei + NEDGES;
    float s0 = 0.f, s1 = 0.f, s2 = 0.f, s3 = 0.f;
    int stride = gridDim.x * blockDim.x;
    for (int e = blockIdx.x * blockDim.x + threadIdx.x; e < NEDGES; e += stride) {
        int s = src[e], d = dst[e];
        atomicAdd(&g_cnt[d], 1);
        float4 as = *(const float4*)(g_asrc + (size_t)s * 4);
        float4 ad = *(const float4*)(g_adst + (size_t)d * 4);
        float4 l;
        l.x = as.x + ad.x; l.y = as.y + ad.y;
        l.z = as.z + ad.z; l.w = as.w + ad.w;
        *(float4*)(g_logits + (size_t)e * 4) = l;
        s0 += __expf(l.x); s1 += __expf(l.y);
        s2 += __expf(l.z); s3 += __expf(l.w);
    }
    __shared__ float red[4][8];
    int lane = threadIdx.x & 31, w = threadIdx.x >> 5;
#pragma unroll
    for (int o = 16; o; o >>= 1) {
        s0 += __shfl_down_sync(0xffffffffu, s0, o);
        s1 += __shfl_down_sync(0xffffffffu, s1, o);
        s2 += __shfl_down_sync(0xffffffffu, s2, o);
        s3 += __shfl_down_sync(0xffffffffu, s3, o);
    }
    if (lane == 0) { red[0][w] = s0; red[1][w] = s1; red[2][w] = s2; red[3][w] = s3; }
    __syncthreads();
    if (threadIdx.x < 4) {
        float ss = 0.f;
#pragma unroll
        for (int i = 0; i < 8; i++) ss += red[threadIdx.x][i];
        atomicAdd(&g_sum[threadIdx.x], ss);
    }
}

// ---------------- K4a/b/c: exclusive scan of g_cnt -> g_base ----------------
__global__ void scan1_kernel() {
    __shared__ int sd[256];
    int t = threadIdx.x;
    int idx = blockIdx.x * 256 + t;
    int v = (idx < NNODES) ? g_cnt[idx] : 0;
    sd[t] = v; __syncthreads();
#pragma unroll
    for (int off = 1; off < 256; off <<= 1) {
        int x = (t >= off) ? sd[t - off] : 0;
        __syncthreads();
        sd[t] += x;
        __syncthreads();
    }
    if (idx < NNODES) g_base[idx] = sd[t] - v;
    if (t == 255) g_part[blockIdx.x] = sd[255];
}
__global__ void scan2_kernel() {
    if (threadIdx.x < NHEADS) g_inv[threadIdx.x] = 1.0f / g_sum[threadIdx.x];
    __shared__ int sd[512];
    int t = threadIdx.x;
    int v = (t < SCAN_B) ? g_part[t] : 0;
    sd[t] = v; __syncthreads();
#pragma unroll
    for (int off = 1; off < 512; off <<= 1) {
        int x = (t >= off) ? sd[t - off] : 0;
        __syncthreads();
        sd[t] += x;
        __syncthreads();
    }
    if (t < SCAN_B) g_poff[t] = sd[t] - v;
    if (t == 0) g_base[NNODES] = NEDGES;
}
__global__ void scan3_kernel() {
    int idx = blockIdx.x * 256 + threadIdx.x;
    if (idx < NNODES) g_base[idx] += g_poff[blockIdx.x];
}

// ---------------- K5: place edges into dst-sorted order ----------------
__global__ void place_kernel(const int* __restrict__ ei) {
    const int* src = ei;
    const int* dst = ei + NEDGES;
    float i0 = g_inv[0], i1 = g_inv[1], i2 = g_inv[2], i3 = g_inv[3];
    int stride = gridDim.x * blockDim.x;
    for (int e = blockIdx.x * blockDim.x + threadIdx.x; e < NEDGES; e += stride) {
        int d = dst[e];
        int pos = g_base[d] + atomicAdd(&g_cnt2[d], 1);
        float4 l = *(const float4*)(g_logits + (size_t)e * 4);
        float4 a;
        a.x = __expf(l.x) * i0;
        a.y = __expf(l.y) * i1;
        a.z = __expf(l.z) * i2;
        a.w = __expf(l.w) * i3;
        g_esrc[pos] = src[e];
        g_ea[pos] = a;
    }
}

// ---------------- K6: warp-per-dst aggregation, out = h + agg ----------------
__global__ void agg_kernel(float* __restrict__ out) {
    int lane = threadIdx.x & 31;
    int w = (blockIdx.x * blockDim.x + threadIdx.x) >> 5;
    int nw = (gridDim.x * blockDim.x) >> 5;
    for (int d = w; d < NNODES; d += nw) {
        int beg = g_base[d], end = g_base[d + 1];
        float a0 = 0.f, a1 = 0.f, a2 = 0.f, a3 = 0.f;
        int p = beg;
        for (; p + 4 <= end; p += 4) {
            int s0 = g_esrc[p], s1 = g_esrc[p + 1], s2 = g_esrc[p + 2], s3 = g_esrc[p + 3];
            float4 w0 = g_ea[p], w1 = g_ea[p + 1], w2 = g_ea[p + 2], w3 = g_ea[p + 3];
            float v0 = g_h[(size_t)s0 * DIM + lane];
            float v1 = g_h[(size_t)s1 * DIM + lane];
            float v2 = g_h[(size_t)s2 * DIM + lane];
            float v3 = g_h[(size_t)s3 * DIM + lane];
            a0 = fmaf(w0.x, v0, fmaf(w1.x, v1, fmaf(w2.x, v2, fmaf(w3.x, v3, a0))));
            a1 = fmaf(w0.y, v0, fmaf(w1.y, v1, fmaf(w2.y, v2, fmaf(w3.y, v3, a1))));
            a2 = fmaf(w0.z, v0, fmaf(w1.z, v1, fmaf(w2.z, v2, fmaf(w3.z, v3, a2))));
            a3 = fmaf(w0.w, v0, fmaf(w1.w, v1, fmaf(w2.w, v2, fmaf(w3.w, v3, a3))));
        }
        for (; p < end; p++) {
            int s = g_esrc[p];
            float4 a = g_ea[p];
            float sv = g_h[(size_t)s * DIM + lane];
            a0 = fmaf(a.x, sv, a0);
            a1 = fmaf(a.y, sv, a1);
            a2 = fmaf(a.z, sv, a2);
            a3 = fmaf(a.w, sv, a3);
        }
        const float* hr = g_h + (size_t)d * DIM;
        float* o = out + (size_t)d * DIM;
        o[lane]      = hr[lane]      + a0;
        o[32 + lane] = hr[32 + lane] + a1;
        o[64 + lane] = hr[64 + lane] + a2;
        o[96 + lane] = hr[96 + lane] + a3;
    }
}

// ---------------- launch ----------------
extern "C" void kernel_launch(void* const* d_in, const int* in_sizes, int n_in,
                              void* d_out, int out_size) {
    const float* feat = (const float*)d_in[0];
    const int*   ei   = (const int*)d_in[1];
    const float* Wlin = (const float*)d_in[2];
    const float* blin = (const float*)d_in[3];
    const float* Watt = (const float*)d_in[4];
    const float* batt = (const float*)d_in[5];
    float* out = (float*)d_out;

    zero_kernel<<<(NNODES + 1023) / 1024, 1024>>>();
    va_kernel<<<1, 1024>>>(Wlin, blin, Watt, batt);
    splitB_kernel<<<(144 * 16 + 255) / 256, 256>>>(Wlin, blin);

    // smem: A(hi+lo) 64KB + B-half(hi+lo) 36KB + bias 288B  => 2 CTAs/SM
    size_t smem = (size_t)(2 * 128 * 128 + 2 * 72 * 128) * sizeof(__nv_bfloat16)
                + 72 * sizeof(float);
    cudaFuncSetAttribute(gemm_kernel, cudaFuncAttributeMaxDynamicSharedMemorySize, (int)smem);
    dim3 ggrid(NTILES, 2);
    gemm_kernel<<<ggrid, 256, smem>>>(feat);

    logits_hist_kernel<<<1184, 256>>>(ei);
    scan1_kernel<<<SCAN_B, 256>>>();
    scan2_kernel<<<1, 512>>>();
    scan3_kernel<<<SCAN_B, 256>>>();
    place_kernel<<<1184, 256>>>(ei);
    agg_kernel<<<1480, 256>>>(out);
}

// round 9
// speedup vs baseline: 3.0778x; 1.1585x over previous
#include <cuda_runtime.h>
#include <cuda_bf16.h>
#include <cstdint>

#define NNODES 100000
#define NEDGES 500000
#define DIM 128
#define NHEADS 4
#define NTILES ((NNODES + 127) / 128)      // 782
#define SCAN_B ((NNODES + 255) / 256)      // 391

// ---------------- scratch ----------------
__device__ float  g_h[NNODES * DIM];           // 51.2 MB
__device__ float  g_asrc[NNODES * NHEADS];
__device__ float  g_adst[NNODES * NHEADS];
__device__ float  g_logits[NEDGES * NHEADS];   // 8 MB
__device__ float  g_va[8 * DIM];               // wa @ W (4 src rows, 4 dst rows)
__device__ float  g_vc[8];                     // b·wa (+ba for dst part)
__device__ float  g_sum[NHEADS];
__device__ float  g_inv[NHEADS];
// pre-split, pre-swizzled B operand (144 rows x 128 cols bf16, hi+lo) + fused bias
__device__ __nv_bfloat16 g_Bhi[144 * 128];
__device__ __nv_bfloat16 g_Blo[144 * 128];
__device__ float  g_bias[144];
// counting-sort scratch
__device__ int    g_cnt[NNODES];
__device__ int    g_cnt2[NNODES];
__device__ int    g_base[NNODES + 1];
__device__ int    g_part[SCAN_B];
__device__ int    g_poff[SCAN_B];
__device__ int    g_esrc[NEDGES];
__device__ float4 g_ea[NEDGES];

// ---------------- helpers ----------------
__device__ __forceinline__ uint32_t smaddr(const void* p) {
    return (uint32_t)__cvta_generic_to_shared(p);
}
__device__ __forceinline__ uint32_t pack_bf(__nv_bfloat16 a, __nv_bfloat16 b) {
    unsigned short ua = *(unsigned short*)&a, ub = *(unsigned short*)&b;
    return (uint32_t)ua | ((uint32_t)ub << 16);
}
// swizzled element offset within a [rows][128] bf16 tile (16B chunk xor swizzle)
__device__ __forceinline__ int swz(int row, int ch) {
    return row * 128 + ((ch ^ (row & 7)) << 3);
}

#define LDSM4(r0, r1, r2, r3, addr) \
    asm volatile("ldmatrix.sync.aligned.m8n8.x4.shared.b16 {%0,%1,%2,%3}, [%4];" \
                 : "=r"(r0), "=r"(r1), "=r"(r2), "=r"(r3) : "r"(addr))
#define LDSM2(r0, r1, addr) \
    asm volatile("ldmatrix.sync.aligned.m8n8.x2.shared.b16 {%0,%1}, [%2];" \
                 : "=r"(r0), "=r"(r1) : "r"(addr))
#define MMA16816(d, a, b0, b1) \
    asm volatile("mma.sync.aligned.m16n8k16.row.col.f32.bf16.bf16.f32 " \
                 "{%0,%1,%2,%3}, {%4,%5,%6,%7}, {%8,%9}, {%0,%1,%2,%3};" \
                 : "+f"(d[0]), "+f"(d[1]), "+f"(d[2]), "+f"(d[3]) \
                 : "r"(a[0]), "r"(a[1]), "r"(a[2]), "r"(a[3]), "r"(b0), "r"(b1))

// ---------------- K0: zero counters ----------------
__global__ void zero_kernel() {
    int i = blockIdx.x * blockDim.x + threadIdx.x;
    if (i < NNODES) { g_cnt[i] = 0; g_cnt2[i] = 0; }
    if (i < NHEADS) g_sum[i] = 0.0f;
}

// ---------------- K0b: va = wa @ W, vc = b·wa (+ba) ----------------
__global__ void va_kernel(const float* __restrict__ W,
                          const float* __restrict__ b,
                          const float* __restrict__ Wa,
                          const float* __restrict__ ba) {
    int t = threadIdx.x;               // 1024 threads
    int j = t >> 7, i = t & 127;
    int head = j & 3, part = j >> 2;
    const float* war = Wa + head * 2 * DIM + part * DIM;
    float s = 0.f;
    for (int k = 0; k < DIM; k++) s += war[k] * W[k * DIM + i];
    g_va[j * DIM + i] = s;
    if (t < 8) {
        int hh = t & 3, pp = t >> 2;
        const float* wr = Wa + hh * 2 * DIM + pp * DIM;
        float c = 0.f;
        for (int k = 0; k < DIM; k++) c += b[k] * wr[k];
        if (pp) c += ba[hh];
        g_vc[t] = c;
    }
}

// ---------------- K0c: pre-split + pre-swizzle B, fuse bias ----------------
__global__ void splitB_kernel(const float* __restrict__ W,
                              const float* __restrict__ b) {
    int idx = blockIdx.x * blockDim.x + threadIdx.x;   // 144*16 items
    if (idx >= 144 * 16) return;
    int row = idx >> 4, ch = idx & 15;
    float v[8];
    if (row < 128) {
        const float4* p = (const float4*)(W + row * 128 + ch * 8);
        float4 a = p[0], c = p[1];
        v[0] = a.x; v[1] = a.y; v[2] = a.z; v[3] = a.w;
        v[4] = c.x; v[5] = c.y; v[6] = c.z; v[7] = c.w;
    } else if (row < 136) {
        const float4* p = (const float4*)(g_va + (row - 128) * 128 + ch * 8);
        float4 a = p[0], c = p[1];
        v[0] = a.x; v[1] = a.y; v[2] = a.z; v[3] = a.w;
        v[4] = c.x; v[5] = c.y; v[6] = c.z; v[7] = c.w;
    } else {
#pragma unroll
        for (int i = 0; i < 8; i++) v[i] = 0.f;
    }
    uint32_t uh[4], ul[4];
#pragma unroll
    for (int i = 0; i < 4; i++) {
        __nv_bfloat16 h0 = __float2bfloat16(v[2 * i]);
        __nv_bfloat16 h1 = __float2bfloat16(v[2 * i + 1]);
        __nv_bfloat16 l0 = __float2bfloat16(v[2 * i] - __bfloat162float(h0));
        __nv_bfloat16 l1 = __float2bfloat16(v[2 * i + 1] - __bfloat162float(h1));
        uh[i] = pack_bf(h0, h1);
        ul[i] = pack_bf(l0, l1);
    }
    int off = swz(row, ch);
    *(uint4*)(g_Bhi + off) = make_uint4(uh[0], uh[1], uh[2], uh[3]);
    *(uint4*)(g_Blo + off) = make_uint4(ul[0], ul[1], ul[2], ul[3]);
    if (idx < 144)
        g_bias[idx] = (idx < 128) ? b[idx] : (idx < 136 ? g_vc[idx - 128] : 0.f);
}

// ---------------- K1: persistent split-bf16 tensor-core GEMM ----------------
// grid = 296 (2 CTAs/SM). Block bx: ny = bx&1 (N-half, 72 cols), tiles strided
// by 148. B staged once per block. MMA sweeps ordered for acc-reuse distance 9.
__global__ void __launch_bounds__(256, 2)
gemm_kernel(const float* __restrict__ feat) {
    extern __shared__ char smraw[];
    __nv_bfloat16* Ahi = (__nv_bfloat16*)smraw;          // 128*128 (32KB)
    __nv_bfloat16* Alo = Ahi + 128 * 128;                // 32KB
    __nv_bfloat16* Bhi = Alo + 128 * 128;                // 72*128 (18KB)
    __nv_bfloat16* Blo = Bhi + 72 * 128;                 // 18KB
    float* sbias = (float*)(Blo + 72 * 128);             // 72

    int tid = threadIdx.x;
    int ny = blockIdx.x & 1;
    int col_base = ny * 72;     // 72 = 8*9, 8-aligned: swizzle slice stays valid

    // ---- stage B once: contiguous pre-swizzled slice ----
    {
        const uint4* srcH = (const uint4*)(g_Bhi + col_base * 128);
        const uint4* srcL = (const uint4*)(g_Blo + col_base * 128);
        for (int i = tid; i < 72 * 128 / 8; i += 256) {
            ((uint4*)Bhi)[i] = srcH[i];
            ((uint4*)Blo)[i] = srcL[i];
        }
        for (int i = tid; i < 72; i += 256) sbias[i] = g_bias[col_base + i];
    }

    int warp = tid >> 5, lane = tid & 31;   // warp = m16 band
    int tq = lane >> 2, tr = lane & 3;

    for (int tile = blockIdx.x >> 1; tile < NTILES; tile += gridDim.x >> 1) {
        int nb = tile * 128;

        // ---- stage A tile: fp32 -> hi/lo bf16 split ----
        for (int idx = tid; idx < 128 * 16; idx += 256) {
            int row = idx >> 4, ch = idx & 15;
            int node = nb + row;
            float v[8];
            if (node < NNODES) {
                const float4* p = (const float4*)(feat + (size_t)node * 128 + ch * 8);
                float4 a = p[0], c = p[1];
                v[0] = a.x; v[1] = a.y; v[2] = a.z; v[3] = a.w;
                v[4] = c.x; v[5] = c.y; v[6] = c.z; v[7] = c.w;
            } else {
#pragma unroll
                for (int i = 0; i < 8; i++) v[i] = 0.f;
            }
            uint32_t uh[4], ul[4];
#pragma unroll
            for (int i = 0; i < 4; i++) {
                __nv_bfloat16 h0 = __float2bfloat16(v[2 * i]);
                __nv_bfloat16 h1 = __float2bfloat16(v[2 * i + 1]);
                __nv_bfloat16 l0 = __float2bfloat16(v[2 * i] - __bfloat162float(h0));
                __nv_bfloat16 l1 = __float2bfloat16(v[2 * i + 1] - __bfloat162float(h1));
                uh[i] = pack_bf(h0, h1);
                ul[i] = pack_bf(l0, l1);
            }
            int off = swz(row, ch);
            *(uint4*)(Ahi + off) = make_uint4(uh[0], uh[1], uh[2], uh[3]);
            *(uint4*)(Alo + off) = make_uint4(ul[0], ul[1], ul[2], ul[3]);
        }
        __syncthreads();

        float acc[9][4];
#pragma unroll
        for (int nt = 0; nt < 9; nt++)
#pragma unroll
            for (int i = 0; i < 4; i++) acc[nt][i] = 0.f;

        for (int ks = 0; ks < 8; ks++) {
            uint32_t ah[4], al[4];
            {
                int row = warp * 16 + (lane & 15);
                int ch = ks * 2 + (lane >> 4);
                uint32_t ad = smaddr(Ahi + swz(row, ch));
                LDSM4(ah[0], ah[1], ah[2], ah[3], ad);
                uint32_t ad2 = smaddr(Alo + swz(row, ch));
                LDSM4(al[0], al[1], al[2], al[3], ad2);
            }
            int rowb_pair = (lane & 7) + ((lane >> 4) << 3);
            int chb = ks * 2 + ((lane >> 3) & 1);

            // load ALL B fragments for this ks first
            uint32_t bh[4][4], bl[4][4], bh8[2], bl8[2];
#pragma unroll
            for (int np = 0; np < 4; np++) {
                int rb = np * 16 + rowb_pair;
                uint32_t bd = smaddr(Bhi + swz(rb, chb));
                LDSM4(bh[np][0], bh[np][1], bh[np][2], bh[np][3], bd);
                uint32_t bd2 = smaddr(Blo + swz(rb, chb));
                LDSM4(bl[np][0], bl[np][1], bl[np][2], bl[np][3], bd2);
            }
            {
                int rb = 64 + (lane & 7);
                uint32_t bd = smaddr(Bhi + swz(rb, chb));
                LDSM2(bh8[0], bh8[1], bd);
                uint32_t bd2 = smaddr(Blo + swz(rb, chb));
                LDSM2(bl8[0], bl8[1], bd2);
            }

            // pass 1: ah x Bhi — 9 independent MMAs
#pragma unroll
            for (int np = 0; np < 4; np++) {
                MMA16816(acc[2 * np],     ah, bh[np][0], bh[np][1]);
                MMA16816(acc[2 * np + 1], ah, bh[np][2], bh[np][3]);
            }
            MMA16816(acc[8], ah, bh8[0], bh8[1]);

            // pass 2: ah x Blo — 9 independent MMAs
#pragma unroll
            for (int np = 0; np < 4; np++) {
                MMA16816(acc[2 * np],     ah, bl[np][0], bl[np][1]);
                MMA16816(acc[2 * np + 1], ah, bl[np][2], bl[np][3]);
            }
            MMA16816(acc[8], ah, bl8[0], bl8[1]);

            // pass 3: al x Bhi — 9 independent MMAs
#pragma unroll
            for (int np = 0; np < 4; np++) {
                MMA16816(acc[2 * np],     al, bh[np][0], bh[np][1]);
                MMA16816(acc[2 * np + 1], al, bh[np][2], bh[np][3]);
            }
            MMA16816(acc[8], al, bh8[0], bh8[1]);
        }

        // ---- epilogue ----
#pragma unroll
        for (int nt = 0; nt < 9; nt++) {
            int col = col_base + nt * 8 + tr * 2;
            if (col >= 136) continue;
            float b0 = sbias[nt * 8 + tr * 2], b1 = sbias[nt * 8 + tr * 2 + 1];
#pragma unroll
            for (int half = 0; half < 2; half++) {
                int node = nb + warp * 16 + tq + half * 8;
                if (node >= NNODES) continue;
                float v0 = acc[nt][half * 2] + b0;
                float v1 = acc[nt][half * 2 + 1] + b1;
                if (col < 128) {
                    float2 o; o.x = v0; o.y = v1;
                    *(float2*)(g_h + (size_t)node * DIM + col) = o;
                } else {
                    int j = col - 128;        // even: 0,2,4,6
                    if (j < 4) {
                        g_asrc[node * NHEADS + j] = v0;
                        g_asrc[node * NHEADS + j + 1] = v1;
                    } else {
                        g_adst[node * NHEADS + j - 4] = v0;
                        g_adst[node * NHEADS + j - 3] = v1;
                    }
                }
            }
        }
        __syncthreads();   // all warps done with A smem before next tile's staging
    }
}

// ---------------- K2: logits + dst histogram + sum(exp) ----------------
__global__ void logits_hist_kernel(const int* __restrict__ ei) {
    const int* src = ei;
    const int* dst = ei + NEDGES;
    float s0 = 0.f, s1 = 0.f, s2 = 0.f, s3 = 0.f;
    int stride = gridDim.x * blockDim.x;
    for (int e = blockIdx.x * blockDim.x + threadIdx.x; e < NEDGES; e += stride) {
        int s = src[e], d = dst[e];
        atomicAdd(&g_cnt[d], 1);
        float4 as = *(const float4*)(g_asrc + (size_t)s * 4);
        float4 ad = *(const float4*)(g_adst + (size_t)d * 4);
        float4 l;
        l.x = as.x + ad.x; l.y = as.y + ad.y;
        l.z = as.z + ad.z; l.w = as.w + ad.w;
        *(float4*)(g_logits + (size_t)e * 4) = l;
        s0 += __expf(l.x); s1 += __expf(l.y);
        s2 += __expf(l.z); s3 += __expf(l.w);
    }
    __shared__ float red[4][8];
    int lane = threadIdx.x & 31, w = threadIdx.x >> 5;
#pragma unroll
    for (int o = 16; o; o >>= 1) {
        s0 += __shfl_down_sync(0xffffffffu, s0, o);
        s1 += __shfl_down_sync(0xffffffffu, s1, o);
        s2 += __shfl_down_sync(0xffffffffu, s2, o);
        s3 += __shfl_down_sync(0xffffffffu, s3, o);
    }
    if (lane == 0) { red[0][w] = s0; red[1][w] = s1; red[2][w] = s2; red[3][w] = s3; }
    __syncthreads();
    if (threadIdx.x < 4) {
        float ss = 0.f;
#pragma unroll
        for (int i = 0; i < 8; i++) ss += red[threadIdx.x][i];
        atomicAdd(&g_sum[threadIdx.x], ss);
    }
}

// ---------------- K4a/b/c: exclusive scan of g_cnt -> g_base ----------------
__global__ void scan1_kernel() {
    __shared__ int sd[256];
    int t = threadIdx.x;
    int idx = blockIdx.x * 256 + t;
    int v = (idx < NNODES) ? g_cnt[idx] : 0;
    sd[t] = v; __syncthreads();
#pragma unroll
    for (int off = 1; off < 256; off <<= 1) {
        int x = (t >= off) ? sd[t - off] : 0;
        __syncthreads();
        sd[t] += x;
        __syncthreads();
    }
    if (idx < NNODES) g_base[idx] = sd[t] - v;
    if (t == 255) g_part[blockIdx.x] = sd[255];
}
__global__ void scan2_kernel() {
    if (threadIdx.x < NHEADS) g_inv[threadIdx.x] = 1.0f / g_sum[threadIdx.x];
    __shared__ int sd[512];
    int t = threadIdx.x;
    int v = (t < SCAN_B) ? g_part[t] : 0;
    sd[t] = v; __syncthreads();
#pragma unroll
    for (int off = 1; off < 512; off <<= 1) {
        int x = (t >= off) ? sd[t - off] : 0;
        __syncthreads();
        sd[t] += x;
        __syncthreads();
    }
    if (t < SCAN_B) g_poff[t] = sd[t] - v;
    if (t == 0) g_base[NNODES] = NEDGES;
}
__global__ void scan3_kernel() {
    int idx = blockIdx.x * 256 + threadIdx.x;
    if (idx < NNODES) g_base[idx] += g_poff[blockIdx.x];
}

// ---------------- K5: place edges into dst-sorted order ----------------
__global__ void place_kernel(const int* __restrict__ ei) {
    const int* src = ei;
    const int* dst = ei + NEDGES;
    float i0 = g_inv[0], i1 = g_inv[1], i2 = g_inv[2], i3 = g_inv[3];
    int stride = gridDim.x * blockDim.x;
    for (int e = blockIdx.x * blockDim.x + threadIdx.x; e < NEDGES; e += stride) {
        int d = dst[e];
        int pos = g_base[d] + atomicAdd(&g_cnt2[d], 1);
        float4 l = *(const float4*)(g_logits + (size_t)e * 4);
        float4 a;
        a.x = __expf(l.x) * i0;
        a.y = __expf(l.y) * i1;
        a.z = __expf(l.z) * i2;
        a.w = __expf(l.w) * i3;
        g_esrc[pos] = src[e];
        g_ea[pos] = a;
    }
}

// ---------------- K6: warp-per-dst aggregation, out = h + agg ----------------
__global__ void agg_kernel(float* __restrict__ out) {
    int lane = threadIdx.x & 31;
    int w = (blockIdx.x * blockDim.x + threadIdx.x) >> 5;
    int nw = (gridDim.x * blockDim.x) >> 5;
    for (int d = w; d < NNODES; d += nw) {
        int beg = g_base[d], end = g_base[d + 1];
        float a0 = 0.f, a1 = 0.f, a2 = 0.f, a3 = 0.f;
        int p = beg;
        for (; p + 4 <= end; p += 4) {
            int s0 = g_esrc[p], s1 = g_esrc[p + 1], s2 = g_esrc[p + 2], s3 = g_esrc[p + 3];
            float4 w0 = g_ea[p], w1 = g_ea[p + 1], w2 = g_ea[p + 2], w3 = g_ea[p + 3];
            float v0 = g_h[(size_t)s0 * DIM + lane];
            float v1 = g_h[(size_t)s1 * DIM + lane];
            float v2 = g_h[(size_t)s2 * DIM + lane];
            float v3 = g_h[(size_t)s3 * DIM + lane];
            a0 = fmaf(w0.x, v0, fmaf(w1.x, v1, fmaf(w2.x, v2, fmaf(w3.x, v3, a0))));
            a1 = fmaf(w0.y, v0, fmaf(w1.y, v1, fmaf(w2.y, v2, fmaf(w3.y, v3, a1))));
            a2 = fmaf(w0.z, v0, fmaf(w1.z, v1, fmaf(w2.z, v2, fmaf(w3.z, v3, a2))));
            a3 = fmaf(w0.w, v0, fmaf(w1.w, v1, fmaf(w2.w, v2, fmaf(w3.w, v3, a3))));
        }
        for (; p < end; p++) {
            int s = g_esrc[p];
            float4 a = g_ea[p];
            float sv = g_h[(size_t)s * DIM + lane];
            a0 = fmaf(a.x, sv, a0);
            a1 = fmaf(a.y, sv, a1);
            a2 = fmaf(a.z, sv, a2);
            a3 = fmaf(a.w, sv, a3);
        }
        const float* hr = g_h + (size_t)d * DIM;
        float* o = out + (size_t)d * DIM;
        o[lane]      = hr[lane]      + a0;
        o[32 + lane] = hr[32 + lane] + a1;
        o[64 + lane] = hr[64 + lane] + a2;
        o[96 + lane] = hr[96 + lane] + a3;
    }
}

// ---------------- launch ----------------
extern "C" void kernel_launch(void* const* d_in, const int* in_sizes, int n_in,
                              void* d_out, int out_size) {
    const float* feat = (const float*)d_in[0];
    const int*   ei   = (const int*)d_in[1];
    const float* Wlin = (const float*)d_in[2];
    const float* blin = (const float*)d_in[3];
    const float* Watt = (const float*)d_in[4];
    const float* batt = (const float*)d_in[5];
    float* out = (float*)d_out;

    zero_kernel<<<(NNODES + 1023) / 1024, 1024>>>();
    va_kernel<<<1, 1024>>>(Wlin, blin, Watt, batt);
    splitB_kernel<<<(144 * 16 + 255) / 256, 256>>>(Wlin, blin);

    // smem: A(hi+lo) 64KB + B-half(hi+lo) 36KB + bias 288B  => 2 CTAs/SM
    size_t smem = (size_t)(2 * 128 * 128 + 2 * 72 * 128) * sizeof(__nv_bfloat16)
                + 72 * sizeof(float);
    cudaFuncSetAttribute(gemm_kernel, cudaFuncAttributeMaxDynamicSharedMemorySize, (int)smem);
    gemm_kernel<<<296, 256, smem>>>(feat);

    logits_hist_kernel<<<1184, 256>>>(ei);
    scan1_kernel<<<SCAN_B, 256>>>();
    scan2_kernel<<<1, 512>>>();
    scan3_kernel<<<SCAN_B, 256>>>();
    place_kernel<<<1184, 256>>>(ei);
    agg_kernel<<<1480, 256>>>(out);
}

// round 10
// speedup vs baseline: 3.1652x; 1.0284x over previous
#include <cuda_runtime.h>
#include <cuda_bf16.h>
#include <cstdint>

#define NNODES 100000
#define NEDGES 500000
#define DIM 128
#define NHEADS 4
#define NTILES ((NNODES + 127) / 128)      // 782
#define SCAN_B ((NNODES + 255) / 256)      // 391

// ---------------- scratch ----------------
__device__ float  g_h[NNODES * DIM];           // 51.2 MB
__device__ float  g_asrc[NNODES * NHEADS];
__device__ float  g_adst[NNODES * NHEADS];
__device__ float  g_logits[NEDGES * NHEADS];   // 8 MB
__device__ float  g_va[8 * DIM];               // wa @ W (4 src rows, 4 dst rows)
__device__ float  g_vc[8];                     // b·wa (+ba for dst part)
__device__ float  g_sum[NHEADS];
__device__ float  g_inv[NHEADS];
// pre-split, pre-swizzled B operand (144 rows x 128 cols bf16, hi+lo) + fused bias
__device__ __nv_bfloat16 g_Bhi[144 * 128];
__device__ __nv_bfloat16 g_Blo[144 * 128];
__device__ float  g_bias[144];
// counting-sort scratch
__device__ int    g_cnt[NNODES];
__device__ int    g_cnt2[NNODES];
__device__ int    g_base[NNODES + 1];
__device__ int    g_part[SCAN_B];
__device__ int    g_poff[SCAN_B];
__device__ int    g_esrc[NEDGES];
__device__ float4 g_ea[NEDGES];

// ---------------- helpers ----------------
__device__ __forceinline__ uint32_t smaddr(const void* p) {
    return (uint32_t)__cvta_generic_to_shared(p);
}
// packed split: v0,v1 -> bf16x2 hi pair + bf16x2 lo pair (identical rounding to
// scalar __float2bfloat16 path, ~6 instrs instead of ~10)
__device__ __forceinline__ void split2(float v0, float v1, uint32_t& hp, uint32_t& lp) {
    asm("cvt.rn.bf16x2.f32 %0, %1, %2;" : "=r"(hp) : "f"(v1), "f"(v0));
    float h0 = __uint_as_float(hp << 16);
    float h1 = __uint_as_float(hp & 0xffff0000u);
    asm("cvt.rn.bf16x2.f32 %0, %1, %2;" : "=r"(lp) : "f"(v1 - h1), "f"(v0 - h0));
}
// swizzled element offset within a [rows][128] bf16 tile (16B chunk xor swizzle)
__device__ __forceinline__ int swz(int row, int ch) {
    return row * 128 + ((ch ^ (row & 7)) << 3);
}

#define LDSM4(r0, r1, r2, r3, addr) \
    asm volatile("ldmatrix.sync.aligned.m8n8.x4.shared.b16 {%0,%1,%2,%3}, [%4];" \
                 : "=r"(r0), "=r"(r1), "=r"(r2), "=r"(r3) : "r"(addr))
#define MMA16816(d, a, b0, b1) \
    asm volatile("mma.sync.aligned.m16n8k16.row.col.f32.bf16.bf16.f32 " \
                 "{%0,%1,%2,%3}, {%4,%5,%6,%7}, {%8,%9}, {%0,%1,%2,%3};" \
                 : "+f"(d[0]), "+f"(d[1]), "+f"(d[2]), "+f"(d[3]) \
                 : "r"(a[0]), "r"(a[1]), "r"(a[2]), "r"(a[3]), "r"(b0), "r"(b1))

// ---------------- K0: zero counters + va (fused) ----------------
__global__ void prep_kernel(const float* __restrict__ W,
                            const float* __restrict__ b,
                            const float* __restrict__ Wa,
                            const float* __restrict__ ba) {
    int i = blockIdx.x * blockDim.x + threadIdx.x;
    if (i < NNODES) { g_cnt[i] = 0; g_cnt2[i] = 0; }
    if (i < NHEADS) g_sum[i] = 0.0f;
    if (blockIdx.x == 0) {      // 1024 threads: va = wa @ W
        int t = threadIdx.x;
        int j = t >> 7, ii = t & 127;
        int head = j & 3, part = j >> 2;
        const float* war = Wa + head * 2 * DIM + part * DIM;
        float s = 0.f;
        for (int k = 0; k < DIM; k++) s += war[k] * W[k * DIM + ii];
        g_va[j * DIM + ii] = s;
        if (t < 8) {
            int hh = t & 3, pp = t >> 2;
            const float* wr = Wa + hh * 2 * DIM + pp * DIM;
            float c = 0.f;
            for (int k = 0; k < DIM; k++) c += b[k] * wr[k];
            if (pp) c += ba[hh];
            g_vc[t] = c;
        }
    }
}

// ---------------- K0c: pre-split + pre-swizzle B, fuse bias ----------------
__global__ void splitB_kernel(const float* __restrict__ W,
                              const float* __restrict__ b) {
    int idx = blockIdx.x * blockDim.x + threadIdx.x;   // 144*16 items
    if (idx >= 144 * 16) return;
    int row = idx >> 4, ch = idx & 15;
    float v[8];
    if (row < 128) {
        const float4* p = (const float4*)(W + row * 128 + ch * 8);
        float4 a = p[0], c = p[1];
        v[0] = a.x; v[1] = a.y; v[2] = a.z; v[3] = a.w;
        v[4] = c.x; v[5] = c.y; v[6] = c.z; v[7] = c.w;
    } else if (row < 136) {
        const float4* p = (const float4*)(g_va + (row - 128) * 128 + ch * 8);
        float4 a = p[0], c = p[1];
        v[0] = a.x; v[1] = a.y; v[2] = a.z; v[3] = a.w;
        v[4] = c.x; v[5] = c.y; v[6] = c.z; v[7] = c.w;
    } else {
#pragma unroll
        for (int i = 0; i < 8; i++) v[i] = 0.f;
    }
    uint32_t uh[4], ul[4];
#pragma unroll
    for (int i = 0; i < 4; i++) split2(v[2 * i], v[2 * i + 1], uh[i], ul[i]);
    int off = swz(row, ch);
    *(uint4*)(g_Bhi + off) = make_uint4(uh[0], uh[1], uh[2], uh[3]);
    *(uint4*)(g_Blo + off) = make_uint4(ul[0], ul[1], ul[2], ul[3]);
    if (idx < 144)
        g_bias[idx] = (idx < 128) ? b[idx] : (idx < 136 ? g_vc[idx - 128] : 0.f);
}

// ---------------- K1: persistent split-bf16 tensor-core GEMM ----------------
// grid = 296 (2 CTAs/SM). Block bx: ny = bx&1 (N-half, 72 cols), tiles strided
// by 148. B staged once per block. MMA sweeps ordered for acc-reuse distance 9.
__global__ void __launch_bounds__(256, 2)
gemm_kernel(const float* __restrict__ feat) {
    extern __shared__ char smraw[];
    __nv_bfloat16* Ahi = (__nv_bfloat16*)smraw;          // 128*128 (32KB)
    __nv_bfloat16* Alo = Ahi + 128 * 128;                // 32KB
    __nv_bfloat16* Bhi = Alo + 128 * 128;                // 72*128 (18KB)
    __nv_bfloat16* Blo = Bhi + 72 * 128;                 // 18KB
    float* sbias = (float*)(Blo + 72 * 128);             // 72

    int tid = threadIdx.x;
    int ny = blockIdx.x & 1;
    int col_base = ny * 72;     // 72 = 8*9, 8-aligned: swizzle slice stays valid

    // ---- stage B once: contiguous pre-swizzled slice ----
    {
        const uint4* srcH = (const uint4*)(g_Bhi + col_base * 128);
        const uint4* srcL = (const uint4*)(g_Blo + col_base * 128);
        for (int i = tid; i < 72 * 128 / 8; i += 256) {
            ((uint4*)Bhi)[i] = srcH[i];
            ((uint4*)Blo)[i] = srcL[i];
        }
        for (int i = tid; i < 72; i += 256) sbias[i] = g_bias[col_base + i];
    }

    int warp = tid >> 5, lane = tid & 31;   // warp = m16 band
    int tq = lane >> 2, tr = lane & 3;

    for (int tile = blockIdx.x >> 1; tile < NTILES; tile += gridDim.x >> 1) {
        int nb = tile * 128;

        // ---- stage A tile: fp32 -> hi/lo bf16 split (packed cvt) ----
        for (int idx = tid; idx < 128 * 16; idx += 256) {
            int row = idx >> 4, ch = idx & 15;
            int node = nb + row;
            float v[8];
            if (node < NNODES) {
                const float4* p = (const float4*)(feat + (size_t)node * 128 + ch * 8);
                float4 a = p[0], c = p[1];
                v[0] = a.x; v[1] = a.y; v[2] = a.z; v[3] = a.w;
                v[4] = c.x; v[5] = c.y; v[6] = c.z; v[7] = c.w;
            } else {
#pragma unroll
                for (int i = 0; i < 8; i++) v[i] = 0.f;
            }
            uint32_t uh[4], ul[4];
#pragma unroll
            for (int i = 0; i < 4; i++) split2(v[2 * i], v[2 * i + 1], uh[i], ul[i]);
            int off = swz(row, ch);
            *(uint4*)(Ahi + off) = make_uint4(uh[0], uh[1], uh[2], uh[3]);
            *(uint4*)(Alo + off) = make_uint4(ul[0], ul[1], ul[2], ul[3]);
        }
        __syncthreads();

        float acc[9][4];
#pragma unroll
        for (int nt = 0; nt < 9; nt++)
#pragma unroll
            for (int i = 0; i < 4; i++) acc[nt][i] = 0.f;

        for (int ks = 0; ks < 8; ks++) {
            uint32_t ah[4], al[4];
            {
                int row = warp * 16 + (lane & 15);
                int ch = ks * 2 + (lane >> 4);
                uint32_t ad = smaddr(Ahi + swz(row, ch));
                LDSM4(ah[0], ah[1], ah[2], ah[3], ad);
                uint32_t ad2 = smaddr(Alo + swz(row, ch));
                LDSM4(al[0], al[1], al[2], al[3], ad2);
            }
            int rowb_pair = (lane & 7) + ((lane >> 4) << 3);
            int chb = ks * 2 + ((lane >> 3) & 1);

            // load ALL B fragments for this ks first
            uint32_t bh[4][4], bl[4][4], bh8[2], bl8[2];
#pragma unroll
            for (int np = 0; np < 4; np++) {
                int rb = np * 16 + rowb_pair;
                uint32_t bd = smaddr(Bhi + swz(rb, chb));
                LDSM4(bh[np][0], bh[np][1], bh[np][2], bh[np][3], bd);
                uint32_t bd2 = smaddr(Blo + swz(rb, chb));
                LDSM4(bl[np][0], bl[np][1], bl[np][2], bl[np][3], bd2);
            }
            {
                // mixed tail: lanes 0-15 -> Bhi, lanes 16-31 -> Blo (one LDSM4)
                int rb = 64 + (lane & 7);
                const __nv_bfloat16* Bt = (lane & 16) ? Blo : Bhi;
                uint32_t bd = smaddr(Bt + swz(rb, chb));
                LDSM4(bh8[0], bh8[1], bl8[0], bl8[1], bd);
            }

            // pass 1: ah x Bhi — 9 independent MMAs
#pragma unroll
            for (int np = 0; np < 4; np++) {
                MMA16816(acc[2 * np],     ah, bh[np][0], bh[np][1]);
                MMA16816(acc[2 * np + 1], ah, bh[np][2], bh[np][3]);
            }
            MMA16816(acc[8], ah, bh8[0], bh8[1]);

            // pass 2: ah x Blo — 9 independent MMAs
#pragma unroll
            for (int np = 0; np < 4; np++) {
                MMA16816(acc[2 * np],     ah, bl[np][0], bl[np][1]);
                MMA16816(acc[2 * np + 1], ah, bl[np][2], bl[np][3]);
            }
            MMA16816(acc[8], ah, bl8[0], bl8[1]);

            // pass 3: al x Bhi — 9 independent MMAs
#pragma unroll
            for (int np = 0; np < 4; np++) {
                MMA16816(acc[2 * np],     al, bh[np][0], bh[np][1]);
                MMA16816(acc[2 * np + 1], al, bh[np][2], bh[np][3]);
            }
            MMA16816(acc[8], al, bh8[0], bh8[1]);
        }

        // ---- epilogue ----
#pragma unroll
        for (int nt = 0; nt < 9; nt++) {
            int col = col_base + nt * 8 + tr * 2;
            if (col >= 136) continue;
            float b0 = sbias[nt * 8 + tr * 2], b1 = sbias[nt * 8 + tr * 2 + 1];
#pragma unroll
            for (int half = 0; half < 2; half++) {
                int node = nb + warp * 16 + tq + half * 8;
                if (node >= NNODES) continue;
                float v0 = acc[nt][half * 2] + b0;
                float v1 = acc[nt][half * 2 + 1] + b1;
                if (col < 128) {
                    float2 o; o.x = v0; o.y = v1;
                    *(float2*)(g_h + (size_t)node * DIM + col) = o;
                } else {
                    int j = col - 128;        // even: 0,2,4,6
                    if (j < 4) {
                        g_asrc[node * NHEADS + j] = v0;
                        g_asrc[node * NHEADS + j + 1] = v1;
                    } else {
                        g_adst[node * NHEADS + j - 4] = v0;
                        g_adst[node * NHEADS + j - 3] = v1;
                    }
                }
            }
        }
        __syncthreads();   // all warps done with A smem before next tile's staging
    }
}

// ---------------- K2: logits + dst histogram + sum(exp) ----------------
__global__ void logits_hist_kernel(const int* __restrict__ ei) {
    const int* src = ei;
    const int* dst = ei + NEDGES;
    float s0 = 0.f, s1 = 0.f, s2 = 0.f, s3 = 0.f;
    int stride = gridDim.x * blockDim.x;
    for (int e = blockIdx.x * blockDim.x + threadIdx.x; e < NEDGES; e += stride) {
        int s = src[e], d = dst[e];
        atomicAdd(&g_cnt[d], 1);
        float4 as = *(const float4*)(g_asrc + (size_t)s * 4);
        float4 ad = *(const float4*)(g_adst + (size_t)d * 4);
        float4 l;
        l.x = as.x + ad.x; l.y = as.y + ad.y;
        l.z = as.z + ad.z; l.w = as.w + ad.w;
        *(float4*)(g_logits + (size_t)e * 4) = l;
        s0 += __expf(l.x); s1 += __expf(l.y);
        s2 += __expf(l.z); s3 += __expf(l.w);
    }
    __shared__ float red[4][8];
    int lane = threadIdx.x & 31, w = threadIdx.x >> 5;
#pragma unroll
    for (int o = 16; o; o >>= 1) {
        s0 += __shfl_down_sync(0xffffffffu, s0, o);
        s1 += __shfl_down_sync(0xffffffffu, s1, o);
        s2 += __shfl_down_sync(0xffffffffu, s2, o);
        s3 += __shfl_down_sync(0xffffffffu, s3, o);
    }
    if (lane == 0) { red[0][w] = s0; red[1][w] = s1; red[2][w] = s2; red[3][w] = s3; }
    __syncthreads();
    if (threadIdx.x < 4) {
        float ss = 0.f;
#pragma unroll
        for (int i = 0; i < 8; i++) ss += red[threadIdx.x][i];
        atomicAdd(&g_sum[threadIdx.x], ss);
    }
}

// ---------------- K4a/b: exclusive scan of g_cnt (block-local + partials) ----
// Final base for index i is g_base[i] + g_poff[i>>8]; scan3 is folded into
// place/agg. scan2 also sets g_base[NNODES] so the formula holds at the end.
__global__ void scan1_kernel() {
    __shared__ int sd[256];
    int t = threadIdx.x;
    int idx = blockIdx.x * 256 + t;
    int v = (idx < NNODES) ? g_cnt[idx] : 0;
    sd[t] = v; __syncthreads();
#pragma unroll
    for (int off = 1; off < 256; off <<= 1) {
        int x = (t >= off) ? sd[t - off] : 0;
        __syncthreads();
        sd[t] += x;
        __syncthreads();
    }
    if (idx < NNODES) g_base[idx] = sd[t] - v;
    if (t == 255) g_part[blockIdx.x] = sd[255];
}
__global__ void scan2_kernel() {
    if (threadIdx.x < NHEADS) g_inv[threadIdx.x] = 1.0f / g_sum[threadIdx.x];
    __shared__ int sd[512];
    int t = threadIdx.x;
    int v = (t < SCAN_B) ? g_part[t] : 0;
    sd[t] = v; __syncthreads();
#pragma unroll
    for (int off = 1; off < 512; off <<= 1) {
        int x = (t >= off) ? sd[t - off] : 0;
        __syncthreads();
        sd[t] += x;
        __syncthreads();
    }
    if (t < SCAN_B) g_poff[t] = sd[t] - v;
    if (t == SCAN_B - 1) g_base[NNODES] = NEDGES - (sd[t] - v);
}

// ---------------- K5: place edges into dst-sorted order ----------------
__global__ void place_kernel(const int* __restrict__ ei) {
    const int* src = ei;
    const int* dst = ei + NEDGES;
    float i0 = g_inv[0], i1 = g_inv[1], i2 = g_inv[2], i3 = g_inv[3];
    int stride = gridDim.x * blockDim.x;
    for (int e = blockIdx.x * blockDim.x + threadIdx.x; e < NEDGES; e += stride) {
        int d = dst[e];
        int pos = g_base[d] + g_poff[d >> 8] + atomicAdd(&g_cnt2[d], 1);
        float4 l = *(const float4*)(g_logits + (size_t)e * 4);
        float4 a;
        a.x = __expf(l.x) * i0;
        a.y = __expf(l.y) * i1;
        a.z = __expf(l.z) * i2;
        a.w = __expf(l.w) * i3;
        g_esrc[pos] = src[e];
        g_ea[pos] = a;
    }
}

// ---------------- K6: warp-per-dst aggregation, out = h + agg ----------------
__global__ void agg_kernel(float* __restrict__ out) {
    int lane = threadIdx.x & 31;
    int w = (blockIdx.x * blockDim.x + threadIdx.x) >> 5;
    int nw = (gridDim.x * blockDim.x) >> 5;
    for (int d = w; d < NNODES; d += nw) {
        int beg = g_base[d] + g_poff[d >> 8];
        int end = g_base[d + 1] + g_poff[(d + 1) >> 8];
        float a0 = 0.f, a1 = 0.f, a2 = 0.f, a3 = 0.f;
        int p = beg;
        for (; p + 4 <= end; p += 4) {
            int s0 = g_esrc[p], s1 = g_esrc[p + 1], s2 = g_esrc[p + 2], s3 = g_esrc[p + 3];
            float4 w0 = g_ea[p], w1 = g_ea[p + 1], w2 = g_ea[p + 2], w3 = g_ea[p + 3];
            float v0 = g_h[(size_t)s0 * DIM + lane];
            float v1 = g_h[(size_t)s1 * DIM + lane];
            float v2 = g_h[(size_t)s2 * DIM + lane];
            float v3 = g_h[(size_t)s3 * DIM + lane];
            a0 = fmaf(w0.x, v0, fmaf(w1.x, v1, fmaf(w2.x, v2, fmaf(w3.x, v3, a0))));
            a1 = fmaf(w0.y, v0, fmaf(w1.y, v1, fmaf(w2.y, v2, fmaf(w3.y, v3, a1))));
            a2 = fmaf(w0.z, v0, fmaf(w1.z, v1, fmaf(w2.z, v2, fmaf(w3.z, v3, a2))));
            a3 = fmaf(w0.w, v0, fmaf(w1.w, v1, fmaf(w2.w, v2, fmaf(w3.w, v3, a3))));
        }
        for (; p < end; p++) {
            int s = g_esrc[p];
            float4 a = g_ea[p];
            float sv = g_h[(size_t)s * DIM + lane];
            a0 = fmaf(a.x, sv, a0);
            a1 = fmaf(a.y, sv, a1);
            a2 = fmaf(a.z, sv, a2);
            a3 = fmaf(a.w, sv, a3);
        }
        const float* hr = g_h + (size_t)d * DIM;
        float* o = out + (size_t)d * DIM;
        o[lane]      = hr[lane]      + a0;
        o[32 + lane] = hr[32 + lane] + a1;
        o[64 + lane] = hr[64 + lane] + a2;
        o[96 + lane] = hr[96 + lane] + a3;
    }
}

// ---------------- launch ----------------
extern "C" void kernel_launch(void* const* d_in, const int* in_sizes, int n_in,
                              void* d_out, int out_size) {
    const float* feat = (const float*)d_in[0];
    const int*   ei   = (const int*)d_in[1];
    const float* Wlin = (const float*)d_in[2];
    const float* blin = (const float*)d_in[3];
    const float* Watt = (const float*)d_in[4];
    const float* batt = (const float*)d_in[5];
    float* out = (float*)d_out;

    prep_kernel<<<(NNODES + 1023) / 1024, 1024>>>(Wlin, blin, Watt, batt);
    splitB_kernel<<<(144 * 16 + 255) / 256, 256>>>(Wlin, blin);

    // smem: A(hi+lo) 64KB + B-half(hi+lo) 36KB + bias 288B  => 2 CTAs/SM
    size_t smem = (size_t)(2 * 128 * 128 + 2 * 72 * 128) * sizeof(__nv_bfloat16)
                + 72 * sizeof(float);
    cudaFuncSetAttribute(gemm_kernel, cudaFuncAttributeMaxDynamicSharedMemorySize, (int)smem);
    gemm_kernel<<<296, 256, smem>>>(feat);

    logits_hist_kernel<<<1184, 256>>>(ei);
    scan1_kernel<<<SCAN_B, 256>>>();
    scan2_kernel<<<1, 512>>>();
    place_kernel<<<1184, 256>>>(ei);
    agg_kernel<<<1480, 256>>>(out);
}